// round 3
// baseline (speedup 1.0000x reference)
#include <cuda_runtime.h>

#define DD 128
#define NMAX 100000
#define EMAX 3200000
#define EPS 1e-5f
#define ROWS 64
#define APITCH 260   // A tile pitch in floats

// ---------------- scratch (no cudaMalloc allowed) ----------------
__device__ __align__(16) float g_neigh[(size_t)NMAX * DD];
__device__ int g_esrc[EMAX];
__device__ int g_cnt[NMAX];
__device__ int g_off[NMAX + 1];
__device__ int g_cur[NMAX];
__device__ float g_sum[DD];
__device__ float g_sumsq[DD];
__device__ __align__(16) float g_stats[2 * DD];   // [0:128) mean, [128:256) rstd
__device__ int g_is64;

// index accessor: int64 (little-endian, values < 2^31) -> low word at 2*i
__device__ __forceinline__ int edge_idx(const int* __restrict__ p, int i) {
    return g_is64 ? p[2 * i] : p[i];
}

// ---------------- K-1: dtype probe ----------------
__global__ void k_detect(const int* __restrict__ s, const int* __restrict__ d, int e) {
    if (threadIdx.x == 0 && blockIdx.x == 0) {
        int m = e < 64 ? e : 64;
        int odd = 0;
        for (int i = 0; i < m; i++) odd |= s[2 * i + 1] | d[2 * i + 1];
        g_is64 = (odd == 0) ? 1 : 0;
    }
}

// ---------------- K0: zero counters ----------------
__global__ void k_zero(int n) {
    int tid = blockIdx.x * blockDim.x + threadIdx.x;
    int nt = gridDim.x * blockDim.x;
    for (int i = tid; i < n; i += nt) g_cnt[i] = 0;
    if (tid < DD) { g_sum[tid] = 0.f; g_sumsq[tid] = 0.f; }
}

// ---------------- K1: degree histogram ----------------
__global__ void k_hist(const int* __restrict__ dst, int e, int n) {
    int i = blockIdx.x * blockDim.x + threadIdx.x;
    if (i >= e) return;
    int d = edge_idx(dst, i);
    if ((unsigned)d < (unsigned)n) atomicAdd(&g_cnt[d], 1);
}

// ---------------- K2: exclusive prefix scan (single block) ----------------
__global__ void __launch_bounds__(1024) k_scan(int n) {
    __shared__ int sdata[1024];
    __shared__ int carry_s;
    int tid = threadIdx.x;
    if (tid == 0) { carry_s = 0; g_off[0] = 0; }
    __syncthreads();
    for (int base = 0; base < n; base += 1024) {
        int i = base + tid;
        int v = (i < n) ? g_cnt[i] : 0;
        sdata[tid] = v;
        __syncthreads();
        for (int off = 1; off < 1024; off <<= 1) {
            int t = (tid >= off) ? sdata[tid - off] : 0;
            __syncthreads();
            sdata[tid] += t;
            __syncthreads();
        }
        int carry = carry_s;
        if (i < n) g_off[i + 1] = carry + sdata[tid];
        __syncthreads();
        if (tid == 1023) carry_s = carry + sdata[1023];
        __syncthreads();
    }
}

// ---------------- K3: init cursors ----------------
__global__ void k_initcur(int n) {
    int i = blockIdx.x * blockDim.x + threadIdx.x;
    if (i < n) g_cur[i] = g_off[i];
}

// ---------------- K4: bucket fill ----------------
__global__ void k_fill(const int* __restrict__ src,
                       const int* __restrict__ dst, int e, int n) {
    int i = blockIdx.x * blockDim.x + threadIdx.x;
    if (i >= e) return;
    int d = edge_idx(dst, i);
    int s = edge_idx(src, i);
    if ((unsigned)d >= (unsigned)n || (unsigned)s >= (unsigned)n) return;
    int pos = atomicAdd(&g_cur[d], 1);
    if ((unsigned)pos < (unsigned)EMAX) g_esrc[pos] = s;
}

// ---------------- K5: warp-per-node gather + mean ----------------
__global__ void k_gather(const float* __restrict__ h, int n) {
    int gw = (blockIdx.x * blockDim.x + threadIdx.x) >> 5;
    int lane = threadIdx.x & 31;
    if (gw >= n) return;
    int o0 = g_off[gw], o1 = g_off[gw + 1];
    const float4* h4 = (const float4*)h;
    float4 acc = make_float4(0.f, 0.f, 0.f, 0.f);
    for (int jb = o0; jb < o1; jb += 32) {
        int myv = (jb + lane < o1) ? g_esrc[jb + lane] : 0;
        int cnt = min(32, o1 - jb);
        for (int k = 0; k < cnt; k++) {
            int s = __shfl_sync(0xffffffffu, myv, k);
            float4 v = h4[s * 32 + lane];
            acc.x += v.x; acc.y += v.y; acc.z += v.z; acc.w += v.w;
        }
    }
    float inv = 1.0f / fmaxf((float)(o1 - o0), 1.0f);
    acc.x *= inv; acc.y *= inv; acc.z *= inv; acc.w *= inv;
    ((float4*)g_neigh)[gw * 32 + lane] = acc;
}

// ---------------- K6: fused dual-GEMM + bias + relu + BN partial sums ----------------
// A = [h | neigh]  (K = 256), W = [W_self ; W_neigh]  (256 x 128)
__global__ void __launch_bounds__(256, 1) k_gemm(
    const float* __restrict__ h, const float* __restrict__ Wself,
    const float* __restrict__ Wneigh, const float* __restrict__ bias,
    float* __restrict__ out, int n)
{
    extern __shared__ float sm[];
    float* Ws = sm;                  // 256 * 128 floats
    float* As = sm + 256 * DD;       // 64 * APITCH floats
    int tid = threadIdx.x;
    int row0 = blockIdx.x * ROWS;

    for (int i = tid; i < 256 * (DD / 4); i += 256) {
        int k = i >> 5, j4 = i & 31;
        float4 v = (k < DD) ? ((const float4*)Wself)[k * (DD / 4) + j4]
                            : ((const float4*)Wneigh)[(k - DD) * (DD / 4) + j4];
        *(float4*)&Ws[k * DD + j4 * 4] = v;
    }
    for (int i = tid; i < ROWS * 64; i += 256) {
        int r = i >> 6, kk = i & 63;
        int rg = row0 + r;
        float4 v = make_float4(0.f, 0.f, 0.f, 0.f);
        if (rg < n) {
            if (kk < 32) v = ((const float4*)h)[rg * 32 + kk];
            else         v = ((const float4*)g_neigh)[rg * 32 + (kk - 32)];
        }
        *(float4*)&As[r * APITCH + kk * 4] = v;
    }
    __syncthreads();

    int tx = tid & 15, ty = tid >> 4;
    const float* a_base = &As[(ty * 4) * APITCH];
    float acc[4][8];
    #pragma unroll
    for (int i = 0; i < 4; i++)
        #pragma unroll
        for (int j = 0; j < 8; j++) acc[i][j] = 0.f;

    #pragma unroll 4
    for (int k = 0; k < 256; k++) {
        float a[4];
        #pragma unroll
        for (int i = 0; i < 4; i++) a[i] = a_base[i * APITCH + k];
        float4 w0 = *(const float4*)&Ws[k * DD + tx * 4];
        float4 w1 = *(const float4*)&Ws[k * DD + 64 + tx * 4];
        #pragma unroll
        for (int i = 0; i < 4; i++) {
            acc[i][0] += a[i] * w0.x; acc[i][1] += a[i] * w0.y;
            acc[i][2] += a[i] * w0.z; acc[i][3] += a[i] * w0.w;
            acc[i][4] += a[i] * w1.x; acc[i][5] += a[i] * w1.y;
            acc[i][6] += a[i] * w1.z; acc[i][7] += a[i] * w1.w;
        }
    }

    float4 b0 = ((const float4*)bias)[tx];
    float4 b1 = ((const float4*)bias)[16 + tx];
    float csum[8], csq[8];
    #pragma unroll
    for (int j = 0; j < 8; j++) { csum[j] = 0.f; csq[j] = 0.f; }

    #pragma unroll
    for (int i = 0; i < 4; i++) {
        int rg = row0 + ty * 4 + i;
        if (rg < n) {
            float r[8];
            r[0] = fmaxf(acc[i][0] + b0.x, 0.f);
            r[1] = fmaxf(acc[i][1] + b0.y, 0.f);
            r[2] = fmaxf(acc[i][2] + b0.z, 0.f);
            r[3] = fmaxf(acc[i][3] + b0.w, 0.f);
            r[4] = fmaxf(acc[i][4] + b1.x, 0.f);
            r[5] = fmaxf(acc[i][5] + b1.y, 0.f);
            r[6] = fmaxf(acc[i][6] + b1.z, 0.f);
            r[7] = fmaxf(acc[i][7] + b1.w, 0.f);
            *(float4*)&out[(size_t)rg * DD + tx * 4]      = make_float4(r[0], r[1], r[2], r[3]);
            *(float4*)&out[(size_t)rg * DD + 64 + tx * 4] = make_float4(r[4], r[5], r[6], r[7]);
            #pragma unroll
            for (int j = 0; j < 8; j++) { csum[j] += r[j]; csq[j] += r[j] * r[j]; }
        }
    }

    __syncthreads();
    float* sred  = sm;             // 16 * 128
    float* sqred = sm + 16 * DD;   // 16 * 128
    #pragma unroll
    for (int j = 0; j < 8; j++) {
        int col = (j < 4) ? (tx * 4 + j) : (64 + tx * 4 + (j - 4));
        sred[ty * DD + col]  = csum[j];
        sqred[ty * DD + col] = csq[j];
    }
    __syncthreads();
    if (tid < DD) {
        float s = 0.f;
        #pragma unroll
        for (int t = 0; t < 16; t++) s += sred[t * DD + tid];
        atomicAdd(&g_sum[tid], s);
    } else {
        int c = tid - DD;
        float s = 0.f;
        #pragma unroll
        for (int t = 0; t < 16; t++) s += sqred[t * DD + c];
        atomicAdd(&g_sumsq[c], s);
    }
}

// ---------------- K7: BN stats ----------------
__global__ void k_stats(float inv_n) {
    int c = threadIdx.x;
    float mean = g_sum[c] * inv_n;
    float var = g_sumsq[c] * inv_n - mean * mean;
    g_stats[c] = mean;
    g_stats[DD + c] = rsqrtf(var + EPS);
}

// ---------------- K8: normalize + residual ----------------
__global__ void k_final(const float* __restrict__ h, const float* __restrict__ gamma,
                        const float* __restrict__ beta, float* __restrict__ out, int n) {
    int i = blockIdx.x * blockDim.x + threadIdx.x;
    int total = n * (DD / 4);
    if (i >= total) return;
    int j4 = i & 31;
    float4 v  = ((float4*)out)[i];
    float4 hv = ((const float4*)h)[i];
    float4 mu = ((const float4*)g_stats)[j4];
    float4 rs = ((const float4*)(g_stats + DD))[j4];
    float4 ga = ((const float4*)gamma)[j4];
    float4 be = ((const float4*)beta)[j4];
    v.x = hv.x + (v.x - mu.x) * rs.x * ga.x + be.x;
    v.y = hv.y + (v.y - mu.y) * rs.y * ga.y + be.y;
    v.z = hv.z + (v.z - mu.z) * rs.z * ga.z + be.z;
    v.w = hv.w + (v.w - mu.w) * rs.w * ga.w + be.w;
    ((float4*)out)[i] = v;
}

// ---------------- launch ----------------
extern "C" void kernel_launch(void* const* d_in, const int* in_sizes, int n_in,
                              void* d_out, int out_size) {
    const float* h     = (const float*)d_in[0];
    const int*   src   = (const int*)d_in[1];
    const int*   dst   = (const int*)d_in[2];
    const float* Wself = (const float*)d_in[3];
    const float* Wneigh= (const float*)d_in[4];
    const float* bias  = (const float*)d_in[5];
    const float* gamma = (const float*)d_in[6];
    const float* beta  = (const float*)d_in[7];
    float* out = (float*)d_out;
    int n = in_sizes[0] / DD;
    int e = in_sizes[1];

    k_detect<<<1, 32>>>(src, dst, e);
    k_zero<<<512, 256>>>(n);
    k_hist<<<(e + 255) / 256, 256>>>(dst, e, n);
    k_scan<<<1, 1024>>>(n);
    k_initcur<<<(n + 255) / 256, 256>>>(n);
    k_fill<<<(e + 255) / 256, 256>>>(src, dst, e, n);
    k_gather<<<(n * 32 + 255) / 256, 256>>>(h, n);

    size_t smem = (size_t)(256 * DD + ROWS * APITCH) * sizeof(float);
    cudaFuncSetAttribute(k_gemm, cudaFuncAttributeMaxDynamicSharedMemorySize, (int)smem);
    k_gemm<<<(n + ROWS - 1) / ROWS, 256, smem>>>(h, Wself, Wneigh, bias, out, n);

    k_stats<<<1, DD>>>(1.0f / (float)n);
    k_final<<<(n * (DD / 4) + 255) / 256, 256>>>(h, gamma, beta, out, n);
}

// round 4
// speedup vs baseline: 1.2692x; 1.2692x over previous
#include <cuda_runtime.h>

#define DD 128
#define NMAX 100000
#define EMAX 3200000
#define EPS 1e-5f
#define ROWS 64
#define APITCH 260   // A tile pitch in floats
#define SCAN_B 1024
#define MAXPARTS 128 // ceil(NMAX/1024) = 98

// ---------------- scratch (no cudaMalloc allowed) ----------------
__device__ __align__(16) float g_neigh[(size_t)NMAX * DD];
__device__ int g_esrc[EMAX];
__device__ int g_cnt[NMAX];
__device__ int g_off[NMAX + 1];
__device__ int g_cur[NMAX];
__device__ int g_part[MAXPARTS];
__device__ float g_sum[DD];
__device__ float g_sumsq[DD];
__device__ __align__(16) float g_stats[2 * DD];   // [0:128) mean, [128:256) rstd
__device__ int g_is64;

// index accessor: int64 (little-endian, values < 2^31) -> low word at 2*i
__device__ __forceinline__ int edge_idx(const int* __restrict__ p, int i) {
    return g_is64 ? p[2 * i] : p[i];
}

// ---------------- dtype probe ----------------
__global__ void k_detect(const int* __restrict__ s, const int* __restrict__ d, int e) {
    if (threadIdx.x == 0 && blockIdx.x == 0) {
        int m = e < 64 ? e : 64;
        int odd = 0;
        for (int i = 0; i < m; i++) odd |= s[2 * i + 1] | d[2 * i + 1];
        g_is64 = (odd == 0) ? 1 : 0;
    }
}

// ---------------- zero counters ----------------
__global__ void k_zero(int n) {
    int tid = blockIdx.x * blockDim.x + threadIdx.x;
    int nt = gridDim.x * blockDim.x;
    for (int i = tid; i < n; i += nt) g_cnt[i] = 0;
    if (tid < DD) { g_sum[tid] = 0.f; g_sumsq[tid] = 0.f; }
}

// ---------------- degree histogram ----------------
__global__ void k_hist(const int* __restrict__ dst, int e, int n) {
    int i = blockIdx.x * blockDim.x + threadIdx.x;
    if (i >= e) return;
    int d = edge_idx(dst, i);
    if ((unsigned)d < (unsigned)n) atomicAdd(&g_cnt[d], 1);
}

// ---------------- decoupled scan: phase 1 (local inclusive scan per block) ----
__global__ void __launch_bounds__(SCAN_B) k_scan1(int n) {
    __shared__ int sdata[SCAN_B];
    int tid = threadIdx.x;
    int i = blockIdx.x * SCAN_B + tid;
    int v = (i < n) ? g_cnt[i] : 0;
    sdata[tid] = v;
    __syncthreads();
    #pragma unroll
    for (int off = 1; off < SCAN_B; off <<= 1) {
        int t = (tid >= off) ? sdata[tid - off] : 0;
        __syncthreads();
        sdata[tid] += t;
        __syncthreads();
    }
    if (i < n) g_off[i + 1] = sdata[tid];   // local inclusive, carry added in phase 3
    if (tid == SCAN_B - 1) g_part[blockIdx.x] = sdata[tid];
}

// ---------------- phase 2: exclusive scan of block partials (1 small block) ----
__global__ void __launch_bounds__(MAXPARTS) k_scan2(int nblocks) {
    __shared__ int sdata[MAXPARTS];
    int tid = threadIdx.x;
    int v = (tid < nblocks) ? g_part[tid] : 0;
    sdata[tid] = v;
    __syncthreads();
    #pragma unroll
    for (int off = 1; off < MAXPARTS; off <<= 1) {
        int t = (tid >= off) ? sdata[tid - off] : 0;
        __syncthreads();
        sdata[tid] += t;
        __syncthreads();
    }
    if (tid < nblocks) g_part[tid] = sdata[tid] - v;   // exclusive
}

// ---------------- phase 3: add carry, write g_off[0] and cursors ----------------
__global__ void __launch_bounds__(SCAN_B) k_scan3(int n) {
    int i = blockIdx.x * SCAN_B + threadIdx.x;
    if (i >= n) return;
    int carry = g_part[blockIdx.x];
    int incl = g_off[i + 1] + carry;
    g_off[i + 1] = incl;
    g_cur[i] = incl - g_cnt[i];   // exclusive offset = cursor start
    if (i == 0) g_off[0] = 0;
}

// ---------------- bucket fill ----------------
__global__ void k_fill(const int* __restrict__ src,
                       const int* __restrict__ dst, int e, int n) {
    int i = blockIdx.x * blockDim.x + threadIdx.x;
    if (i >= e) return;
    int d = edge_idx(dst, i);
    int s = edge_idx(src, i);
    if ((unsigned)d >= (unsigned)n || (unsigned)s >= (unsigned)n) return;
    int pos = atomicAdd(&g_cur[d], 1);
    if ((unsigned)pos < (unsigned)EMAX) g_esrc[pos] = s;
}

// ---------------- warp-per-node gather + mean ----------------
__global__ void k_gather(const float* __restrict__ h, int n) {
    int gw = (blockIdx.x * blockDim.x + threadIdx.x) >> 5;
    int lane = threadIdx.x & 31;
    if (gw >= n) return;
    int o0 = g_off[gw], o1 = g_off[gw + 1];
    const float4* h4 = (const float4*)h;
    float4 acc = make_float4(0.f, 0.f, 0.f, 0.f);
    for (int jb = o0; jb < o1; jb += 32) {
        int myv = (jb + lane < o1) ? g_esrc[jb + lane] : 0;
        int cnt = min(32, o1 - jb);
        for (int k = 0; k < cnt; k++) {
            int s = __shfl_sync(0xffffffffu, myv, k);
            float4 v = h4[s * 32 + lane];
            acc.x += v.x; acc.y += v.y; acc.z += v.z; acc.w += v.w;
        }
    }
    float inv = 1.0f / fmaxf((float)(o1 - o0), 1.0f);
    acc.x *= inv; acc.y *= inv; acc.z *= inv; acc.w *= inv;
    ((float4*)g_neigh)[gw * 32 + lane] = acc;
}

// ---------------- fused dual-GEMM + bias + relu + BN partial sums ----------------
// A = [h | neigh]  (K = 256), W = [W_self ; W_neigh]  (256 x 128)
__global__ void __launch_bounds__(256, 1) k_gemm(
    const float* __restrict__ h, const float* __restrict__ Wself,
    const float* __restrict__ Wneigh, const float* __restrict__ bias,
    float* __restrict__ out, int n)
{
    extern __shared__ float sm[];
    float* Ws = sm;                  // 256 * 128 floats
    float* As = sm + 256 * DD;       // 64 * APITCH floats
    int tid = threadIdx.x;
    int row0 = blockIdx.x * ROWS;

    for (int i = tid; i < 256 * (DD / 4); i += 256) {
        int k = i >> 5, j4 = i & 31;
        float4 v = (k < DD) ? ((const float4*)Wself)[k * (DD / 4) + j4]
                            : ((const float4*)Wneigh)[(k - DD) * (DD / 4) + j4];
        *(float4*)&Ws[k * DD + j4 * 4] = v;
    }
    for (int i = tid; i < ROWS * 64; i += 256) {
        int r = i >> 6, kk = i & 63;
        int rg = row0 + r;
        float4 v = make_float4(0.f, 0.f, 0.f, 0.f);
        if (rg < n) {
            if (kk < 32) v = ((const float4*)h)[rg * 32 + kk];
            else         v = ((const float4*)g_neigh)[rg * 32 + (kk - 32)];
        }
        *(float4*)&As[r * APITCH + kk * 4] = v;
    }
    __syncthreads();

    int tx = tid & 15, ty = tid >> 4;
    const float* a_base = &As[(ty * 4) * APITCH];
    float acc[4][8];
    #pragma unroll
    for (int i = 0; i < 4; i++)
        #pragma unroll
        for (int j = 0; j < 8; j++) acc[i][j] = 0.f;

    #pragma unroll 4
    for (int k = 0; k < 256; k++) {
        float a[4];
        #pragma unroll
        for (int i = 0; i < 4; i++) a[i] = a_base[i * APITCH + k];
        float4 w0 = *(const float4*)&Ws[k * DD + tx * 4];
        float4 w1 = *(const float4*)&Ws[k * DD + 64 + tx * 4];
        #pragma unroll
        for (int i = 0; i < 4; i++) {
            acc[i][0] += a[i] * w0.x; acc[i][1] += a[i] * w0.y;
            acc[i][2] += a[i] * w0.z; acc[i][3] += a[i] * w0.w;
            acc[i][4] += a[i] * w1.x; acc[i][5] += a[i] * w1.y;
            acc[i][6] += a[i] * w1.z; acc[i][7] += a[i] * w1.w;
        }
    }

    float4 b0 = ((const float4*)bias)[tx];
    float4 b1 = ((const float4*)bias)[16 + tx];
    float csum[8], csq[8];
    #pragma unroll
    for (int j = 0; j < 8; j++) { csum[j] = 0.f; csq[j] = 0.f; }

    #pragma unroll
    for (int i = 0; i < 4; i++) {
        int rg = row0 + ty * 4 + i;
        if (rg < n) {
            float r[8];
            r[0] = fmaxf(acc[i][0] + b0.x, 0.f);
            r[1] = fmaxf(acc[i][1] + b0.y, 0.f);
            r[2] = fmaxf(acc[i][2] + b0.z, 0.f);
            r[3] = fmaxf(acc[i][3] + b0.w, 0.f);
            r[4] = fmaxf(acc[i][4] + b1.x, 0.f);
            r[5] = fmaxf(acc[i][5] + b1.y, 0.f);
            r[6] = fmaxf(acc[i][6] + b1.z, 0.f);
            r[7] = fmaxf(acc[i][7] + b1.w, 0.f);
            *(float4*)&out[(size_t)rg * DD + tx * 4]      = make_float4(r[0], r[1], r[2], r[3]);
            *(float4*)&out[(size_t)rg * DD + 64 + tx * 4] = make_float4(r[4], r[5], r[6], r[7]);
            #pragma unroll
            for (int j = 0; j < 8; j++) { csum[j] += r[j]; csq[j] += r[j] * r[j]; }
        }
    }

    __syncthreads();
    float* sred  = sm;             // 16 * 128
    float* sqred = sm + 16 * DD;   // 16 * 128
    #pragma unroll
    for (int j = 0; j < 8; j++) {
        int col = (j < 4) ? (tx * 4 + j) : (64 + tx * 4 + (j - 4));
        sred[ty * DD + col]  = csum[j];
        sqred[ty * DD + col] = csq[j];
    }
    __syncthreads();
    if (tid < DD) {
        float s = 0.f;
        #pragma unroll
        for (int t = 0; t < 16; t++) s += sred[t * DD + tid];
        atomicAdd(&g_sum[tid], s);
    } else {
        int c = tid - DD;
        float s = 0.f;
        #pragma unroll
        for (int t = 0; t < 16; t++) s += sqred[t * DD + c];
        atomicAdd(&g_sumsq[c], s);
    }
}

// ---------------- BN stats ----------------
__global__ void k_stats(float inv_n) {
    int c = threadIdx.x;
    float mean = g_sum[c] * inv_n;
    float var = g_sumsq[c] * inv_n - mean * mean;
    g_stats[c] = mean;
    g_stats[DD + c] = rsqrtf(var + EPS);
}

// ---------------- normalize + residual ----------------
__global__ void k_final(const float* __restrict__ h, const float* __restrict__ gamma,
                        const float* __restrict__ beta, float* __restrict__ out, int n) {
    int i = blockIdx.x * blockDim.x + threadIdx.x;
    int total = n * (DD / 4);
    if (i >= total) return;
    int j4 = i & 31;
    float4 v  = ((float4*)out)[i];
    float4 hv = ((const float4*)h)[i];
    float4 mu = ((const float4*)g_stats)[j4];
    float4 rs = ((const float4*)(g_stats + DD))[j4];
    float4 ga = ((const float4*)gamma)[j4];
    float4 be = ((const float4*)beta)[j4];
    v.x = hv.x + (v.x - mu.x) * rs.x * ga.x + be.x;
    v.y = hv.y + (v.y - mu.y) * rs.y * ga.y + be.y;
    v.z = hv.z + (v.z - mu.z) * rs.z * ga.z + be.z;
    v.w = hv.w + (v.w - mu.w) * rs.w * ga.w + be.w;
    ((float4*)out)[i] = v;
}

// ---------------- launch ----------------
extern "C" void kernel_launch(void* const* d_in, const int* in_sizes, int n_in,
                              void* d_out, int out_size) {
    const float* h     = (const float*)d_in[0];
    const int*   src   = (const int*)d_in[1];
    const int*   dst   = (const int*)d_in[2];
    const float* Wself = (const float*)d_in[3];
    const float* Wneigh= (const float*)d_in[4];
    const float* bias  = (const float*)d_in[5];
    const float* gamma = (const float*)d_in[6];
    const float* beta  = (const float*)d_in[7];
    float* out = (float*)d_out;
    int n = in_sizes[0] / DD;
    int e = in_sizes[1];

    int nscan = (n + SCAN_B - 1) / SCAN_B;

    k_detect<<<1, 32>>>(src, dst, e);
    k_zero<<<512, 256>>>(n);
    k_hist<<<(e + 255) / 256, 256>>>(dst, e, n);
    k_scan1<<<nscan, SCAN_B>>>(n);
    k_scan2<<<1, MAXPARTS>>>(nscan);
    k_scan3<<<nscan, SCAN_B>>>(n);
    k_fill<<<(e + 255) / 256, 256>>>(src, dst, e, n);
    k_gather<<<(n * 32 + 255) / 256, 256>>>(h, n);

    size_t smem = (size_t)(256 * DD + ROWS * APITCH) * sizeof(float);
    cudaFuncSetAttribute(k_gemm, cudaFuncAttributeMaxDynamicSharedMemorySize, (int)smem);
    k_gemm<<<(n + ROWS - 1) / ROWS, 256, smem>>>(h, Wself, Wneigh, bias, out, n);

    k_stats<<<1, DD>>>(1.0f / (float)n);
    k_final<<<(n * (DD / 4) + 255) / 256, 256>>>(h, gamma, beta, out, n);
}

// round 5
// speedup vs baseline: 1.7678x; 1.3929x over previous
#include <cuda_runtime.h>
#include <cstdint>

#define DD 128
#define NMAX 100000
#define EMAX 3200000
#define EPS 1e-5f
#define SCAN_B 1024
#define MAXPARTS 128
#define NSM 148
#define MT 64          // rows per GEMM tile
#define WPITCH 136     // Ws pitch (floats): 8t+g bank pattern -> conflict-free
#define APITCH 260     // As pitch (floats): 4g+t bank pattern -> conflict-free

// ---------------- scratch (no cudaMalloc allowed) ----------------
__device__ __align__(16) float g_neigh[(size_t)NMAX * DD];
__device__ int g_esrc[EMAX];
__device__ int g_cnt[NMAX];
__device__ int g_off[NMAX + 1];
__device__ int g_cur[NMAX];
__device__ int g_part[MAXPARTS];
__device__ float g_sum[DD];
__device__ float g_sumsq[DD];
__device__ __align__(16) float g_stats[2 * DD];
__device__ int g_is64;

__device__ __forceinline__ int edge_idx(const int* __restrict__ p, int i) {
    return g_is64 ? p[2 * i] : p[i];
}

__device__ __forceinline__ unsigned f2tf(float f) {
    unsigned u; asm("cvt.rna.tf32.f32 %0, %1;" : "=r"(u) : "f"(f)); return u;
}

__device__ __forceinline__ void mma_tf32(float* c, const unsigned* a, unsigned b0, unsigned b1) {
    asm volatile("mma.sync.aligned.m16n8k8.row.col.f32.tf32.tf32.f32 "
                 "{%0,%1,%2,%3}, {%4,%5,%6,%7}, {%8,%9}, {%0,%1,%2,%3};"
                 : "+f"(c[0]), "+f"(c[1]), "+f"(c[2]), "+f"(c[3])
                 : "r"(a[0]), "r"(a[1]), "r"(a[2]), "r"(a[3]), "r"(b0), "r"(b1));
}

// ---------------- dtype probe ----------------
__global__ void k_detect(const int* __restrict__ s, const int* __restrict__ d, int e) {
    if (threadIdx.x == 0 && blockIdx.x == 0) {
        int m = e < 64 ? e : 64;
        int odd = 0;
        for (int i = 0; i < m; i++) odd |= s[2 * i + 1] | d[2 * i + 1];
        g_is64 = (odd == 0) ? 1 : 0;
    }
}

// ---------------- zero counters ----------------
__global__ void k_zero(int n) {
    int tid = blockIdx.x * blockDim.x + threadIdx.x;
    int nt = gridDim.x * blockDim.x;
    for (int i = tid; i < n; i += nt) g_cnt[i] = 0;
    if (tid < DD) { g_sum[tid] = 0.f; g_sumsq[tid] = 0.f; }
}

// ---------------- degree histogram ----------------
__global__ void k_hist(const int* __restrict__ dst, int e, int n) {
    int i = blockIdx.x * blockDim.x + threadIdx.x;
    if (i >= e) return;
    int d = edge_idx(dst, i);
    if ((unsigned)d < (unsigned)n) atomicAdd(&g_cnt[d], 1);
}

// ---------------- decoupled scan ----------------
__global__ void __launch_bounds__(SCAN_B) k_scan1(int n) {
    __shared__ int sdata[SCAN_B];
    int tid = threadIdx.x;
    int i = blockIdx.x * SCAN_B + tid;
    int v = (i < n) ? g_cnt[i] : 0;
    sdata[tid] = v;
    __syncthreads();
    #pragma unroll
    for (int off = 1; off < SCAN_B; off <<= 1) {
        int t = (tid >= off) ? sdata[tid - off] : 0;
        __syncthreads();
        sdata[tid] += t;
        __syncthreads();
    }
    if (i < n) g_off[i + 1] = sdata[tid];
    if (tid == SCAN_B - 1) g_part[blockIdx.x] = sdata[tid];
}

__global__ void __launch_bounds__(MAXPARTS) k_scan2(int nblocks) {
    __shared__ int sdata[MAXPARTS];
    int tid = threadIdx.x;
    int v = (tid < nblocks) ? g_part[tid] : 0;
    sdata[tid] = v;
    __syncthreads();
    #pragma unroll
    for (int off = 1; off < MAXPARTS; off <<= 1) {
        int t = (tid >= off) ? sdata[tid - off] : 0;
        __syncthreads();
        sdata[tid] += t;
        __syncthreads();
    }
    if (tid < nblocks) g_part[tid] = sdata[tid] - v;
}

__global__ void __launch_bounds__(SCAN_B) k_scan3(int n) {
    int i = blockIdx.x * SCAN_B + threadIdx.x;
    if (i >= n) return;
    int carry = g_part[blockIdx.x];
    int incl = g_off[i + 1] + carry;
    g_off[i + 1] = incl;
    g_cur[i] = incl - g_cnt[i];
    if (i == 0) g_off[0] = 0;
}

// ---------------- bucket fill ----------------
__global__ void k_fill(const int* __restrict__ src,
                       const int* __restrict__ dst, int e, int n) {
    int i = blockIdx.x * blockDim.x + threadIdx.x;
    if (i >= e) return;
    int d = edge_idx(dst, i);
    int s = edge_idx(src, i);
    if ((unsigned)d >= (unsigned)n || (unsigned)s >= (unsigned)n) return;
    int pos = atomicAdd(&g_cur[d], 1);
    if ((unsigned)pos < (unsigned)EMAX) g_esrc[pos] = s;
}

// ---------------- warp-per-node gather + mean ----------------
__global__ void k_gather(const float* __restrict__ h, int n) {
    int gw = (blockIdx.x * blockDim.x + threadIdx.x) >> 5;
    int lane = threadIdx.x & 31;
    if (gw >= n) return;
    int o0 = g_off[gw], o1 = g_off[gw + 1];
    const float4* h4 = (const float4*)h;
    float4 acc = make_float4(0.f, 0.f, 0.f, 0.f);
    for (int jb = o0; jb < o1; jb += 32) {
        int myv = (jb + lane < o1) ? g_esrc[jb + lane] : 0;
        int cnt = min(32, o1 - jb);
        for (int k = 0; k < cnt; k++) {
            int s = __shfl_sync(0xffffffffu, myv, k);
            float4 v = h4[s * 32 + lane];
            acc.x += v.x; acc.y += v.y; acc.z += v.z; acc.w += v.w;
        }
    }
    float inv = 1.0f / fmaxf((float)(o1 - o0), 1.0f);
    acc.x *= inv; acc.y *= inv; acc.z *= inv; acc.w *= inv;
    ((float4*)g_neigh)[gw * 32 + lane] = acc;
}

// ---------------- tf32 tensor-core dual-GEMM + bias + relu + BN sums ----------------
// Persistent: grid = NSM blocks, each iterates M-tiles (64 rows).
// A = [h | neigh] (K=256), W = [W_self; W_neigh] (256x128) resident in smem.
// 8 warps = 2(m) x 4(n); warp tile 32x32 via mma.m16n8k8 tf32.
__global__ void __launch_bounds__(256, 1) k_gemm_tc(
    const float* __restrict__ h, const float* __restrict__ Wself,
    const float* __restrict__ Wneigh, const float* __restrict__ bias,
    float* __restrict__ out, int n, int ntiles)
{
    extern __shared__ float sm[];
    float* Ws = sm;                    // 256 * WPITCH
    float* As = sm + 256 * WPITCH;     // MT * APITCH
    int tid = threadIdx.x;
    int wid = tid >> 5, lane = tid & 31;
    int g = lane >> 2, t = lane & 3;
    int wm = wid & 1, wn = wid >> 1;
    int colb = wn * 32;

    // stage W once (tf32-converted)
    {
        int row = tid;
        const float* srcw = (row < DD) ? (Wself + row * DD) : (Wneigh + (row - DD) * DD);
        float* dstRow = Ws + row * WPITCH;
        for (int c = 0; c < DD; c += 4) {
            float4 v = *(const float4*)(srcw + c);
            uint4 uu = make_uint4(f2tf(v.x), f2tf(v.y), f2tf(v.z), f2tf(v.w));
            *(uint4*)(dstRow + c) = uu;
        }
    }

    float bs[4][2];
    #pragma unroll
    for (int j = 0; j < 4; j++) {
        bs[j][0] = bias[colb + j * 8 + 2 * t];
        bs[j][1] = bias[colb + j * 8 + 2 * t + 1];
    }
    float csum[4][2] = {{0.f,0.f},{0.f,0.f},{0.f,0.f},{0.f,0.f}};
    float csq [4][2] = {{0.f,0.f},{0.f,0.f},{0.f,0.f},{0.f,0.f}};

    const unsigned* Asu = (const unsigned*)As;
    const unsigned* Wsu = (const unsigned*)Ws;

    for (int tile = blockIdx.x; tile < ntiles; tile += gridDim.x) {
        int m0 = tile * MT;
        __syncthreads();
        // stage A tile (tf32-converted), zeros for OOB rows
        #pragma unroll
        for (int it = 0; it < 16; it++) {
            int f4 = tid + it * 256;          // MT*64 = 4096 float4
            int row = f4 >> 6, c4 = f4 & 63;
            int rg = m0 + row;
            float4 v = make_float4(0.f, 0.f, 0.f, 0.f);
            if (rg < n)
                v = (c4 < 32) ? ((const float4*)h)[rg * 32 + c4]
                              : ((const float4*)g_neigh)[rg * 32 + c4 - 32];
            uint4 uu = make_uint4(f2tf(v.x), f2tf(v.y), f2tf(v.z), f2tf(v.w));
            *(uint4*)(As + row * APITCH + c4 * 4) = uu;
        }
        __syncthreads();

        float acc[2][4][4];
        #pragma unroll
        for (int i = 0; i < 2; i++)
            #pragma unroll
            for (int j = 0; j < 4; j++)
                #pragma unroll
                for (int q = 0; q < 4; q++) acc[i][j][q] = 0.f;

        #pragma unroll 4
        for (int kc = 0; kc < 32; kc++) {
            int k0 = kc * 8;
            unsigned a[2][4];
            #pragma unroll
            for (int i = 0; i < 2; i++) {
                int rb = (wm * 32 + i * 16 + g) * APITCH + k0 + t;
                a[i][0] = Asu[rb];
                a[i][1] = Asu[rb + 8 * APITCH];
                a[i][2] = Asu[rb + 4];
                a[i][3] = Asu[rb + 8 * APITCH + 4];
            }
            #pragma unroll
            for (int j = 0; j < 4; j++) {
                int ba = (k0 + t) * WPITCH + colb + j * 8 + g;
                unsigned b0 = Wsu[ba];
                unsigned b1 = Wsu[ba + 4 * WPITCH];
                mma_tf32(acc[0][j], a[0], b0, b1);
                mma_tf32(acc[1][j], a[1], b0, b1);
            }
        }

        // epilogue: bias + relu + store + BN accumulation (registers)
        #pragma unroll
        for (int i = 0; i < 2; i++) {
            int row0 = m0 + wm * 32 + i * 16 + g;
            #pragma unroll
            for (int j = 0; j < 4; j++) {
                int col = colb + j * 8 + 2 * t;
                float c0 = fmaxf(acc[i][j][0] + bs[j][0], 0.f);
                float c1 = fmaxf(acc[i][j][1] + bs[j][1], 0.f);
                float c2 = fmaxf(acc[i][j][2] + bs[j][0], 0.f);
                float c3 = fmaxf(acc[i][j][3] + bs[j][1], 0.f);
                if (row0 < n) {
                    *(float2*)&out[(size_t)row0 * DD + col] = make_float2(c0, c1);
                    csum[j][0] += c0; csq[j][0] += c0 * c0;
                    csum[j][1] += c1; csq[j][1] += c1 * c1;
                }
                if (row0 + 8 < n) {
                    *(float2*)&out[(size_t)(row0 + 8) * DD + col] = make_float2(c2, c3);
                    csum[j][0] += c2; csq[j][0] += c2 * c2;
                    csum[j][1] += c3; csq[j][1] += c3 * c3;
                }
            }
        }
    }

    // warp-level reduce over g (lanes stride 4), then global atomics
    #pragma unroll
    for (int j = 0; j < 4; j++)
        #pragma unroll
        for (int p = 0; p < 2; p++) {
            float s = csum[j][p], q = csq[j][p];
            #pragma unroll
            for (int off = 16; off >= 4; off >>= 1) {
                s += __shfl_down_sync(0xffffffffu, s, off);
                q += __shfl_down_sync(0xffffffffu, q, off);
            }
            if (g == 0) {
                int col = colb + j * 8 + 2 * t + p;
                atomicAdd(&g_sum[col], s);
                atomicAdd(&g_sumsq[col], q);
            }
        }
}

// ---------------- BN stats ----------------
__global__ void k_stats(float inv_n) {
    int c = threadIdx.x;
    float mean = g_sum[c] * inv_n;
    float var = g_sumsq[c] * inv_n - mean * mean;
    g_stats[c] = mean;
    g_stats[DD + c] = rsqrtf(var + EPS);
}

// ---------------- normalize + residual ----------------
__global__ void k_final(const float* __restrict__ h, const float* __restrict__ gamma,
                        const float* __restrict__ beta, float* __restrict__ out, int n) {
    int i = blockIdx.x * blockDim.x + threadIdx.x;
    int total = n * (DD / 4);
    if (i >= total) return;
    int j4 = i & 31;
    float4 v  = ((float4*)out)[i];
    float4 hv = ((const float4*)h)[i];
    float4 mu = ((const float4*)g_stats)[j4];
    float4 rs = ((const float4*)(g_stats + DD))[j4];
    float4 ga = ((const float4*)gamma)[j4];
    float4 be = ((const float4*)beta)[j4];
    v.x = hv.x + (v.x - mu.x) * rs.x * ga.x + be.x;
    v.y = hv.y + (v.y - mu.y) * rs.y * ga.y + be.y;
    v.z = hv.z + (v.z - mu.z) * rs.z * ga.z + be.z;
    v.w = hv.w + (v.w - mu.w) * rs.w * ga.w + be.w;
    ((float4*)out)[i] = v;
}

// ---------------- launch ----------------
extern "C" void kernel_launch(void* const* d_in, const int* in_sizes, int n_in,
                              void* d_out, int out_size) {
    const float* h     = (const float*)d_in[0];
    const int*   src   = (const int*)d_in[1];
    const int*   dst   = (const int*)d_in[2];
    const float* Wself = (const float*)d_in[3];
    const float* Wneigh= (const float*)d_in[4];
    const float* bias  = (const float*)d_in[5];
    const float* gamma = (const float*)d_in[6];
    const float* beta  = (const float*)d_in[7];
    float* out = (float*)d_out;
    int n = in_sizes[0] / DD;
    int e = in_sizes[1];

    int nscan = (n + SCAN_B - 1) / SCAN_B;

    k_detect<<<1, 32>>>(src, dst, e);
    k_zero<<<512, 256>>>(n);
    k_hist<<<(e + 255) / 256, 256>>>(dst, e, n);
    k_scan1<<<nscan, SCAN_B>>>(n);
    k_scan2<<<1, MAXPARTS>>>(nscan);
    k_scan3<<<nscan, SCAN_B>>>(n);
    k_fill<<<(e + 255) / 256, 256>>>(src, dst, e, n);
    k_gather<<<(n * 32 + 255) / 256, 256>>>(h, n);

    int ntiles = (n + MT - 1) / MT;
    size_t smem = (size_t)(256 * WPITCH + MT * APITCH) * sizeof(float);
    cudaFuncSetAttribute(k_gemm_tc, cudaFuncAttributeMaxDynamicSharedMemorySize, (int)smem);
    k_gemm_tc<<<NSM, 256, smem>>>(h, Wself, Wneigh, bias, out, n, ntiles);

    k_stats<<<1, DD>>>(1.0f / (float)n);
    k_final<<<(n * (DD / 4) + 255) / 256, 256>>>(h, gamma, beta, out, n);
}

// round 6
// speedup vs baseline: 1.7784x; 1.0060x over previous
#include <cuda_runtime.h>
#include <cuda_fp16.h>
#include <cstdint>

#define DD 128
#define NMAX 100000
#define EMAX 3200000
#define EPS 1e-5f
#define SCAN_B 1024
#define MAXPARTS 128
#define NSM 148
#define MT 64          // rows per GEMM tile
#define WPITCH 136     // Ws pitch (floats)
#define APITCH 260     // As pitch (floats)

// ---------------- scratch (no cudaMalloc allowed) ----------------
__device__ __align__(16) float g_neigh[(size_t)NMAX * DD];
__device__ __align__(16) __half g_h16[(size_t)NMAX * DD];
__device__ int g_esrc[EMAX];
__device__ int g_cnt[NMAX];
__device__ int g_off[NMAX + 1];
__device__ int g_cur[NMAX];
__device__ int g_part[MAXPARTS];
__device__ float g_sum[DD];
__device__ float g_sumsq[DD];
__device__ int g_is64;

__device__ __forceinline__ int edge_idx(const int* __restrict__ p, int i) {
    return g_is64 ? p[2 * i] : p[i];
}

__device__ __forceinline__ unsigned f2tf(float f) {
    unsigned u; asm("cvt.rna.tf32.f32 %0, %1;" : "=r"(u) : "f"(f)); return u;
}

__device__ __forceinline__ void mma_tf32(float* c, const unsigned* a, unsigned b0, unsigned b1) {
    asm volatile("mma.sync.aligned.m16n8k8.row.col.f32.tf32.tf32.f32 "
                 "{%0,%1,%2,%3}, {%4,%5,%6,%7}, {%8,%9}, {%0,%1,%2,%3};"
                 : "+f"(c[0]), "+f"(c[1]), "+f"(c[2]), "+f"(c[3])
                 : "r"(a[0]), "r"(a[1]), "r"(a[2]), "r"(a[3]), "r"(b0), "r"(b1));
}

// ---------------- dtype probe ----------------
__global__ void k_detect(const int* __restrict__ s, const int* __restrict__ d, int e) {
    if (threadIdx.x == 0 && blockIdx.x == 0) {
        int m = e < 64 ? e : 64;
        int odd = 0;
        for (int i = 0; i < m; i++) odd |= s[2 * i + 1] | d[2 * i + 1];
        g_is64 = (odd == 0) ? 1 : 0;
    }
}

// ---------------- zero counters ----------------
__global__ void k_zero(int n) {
    int tid = blockIdx.x * blockDim.x + threadIdx.x;
    int nt = gridDim.x * blockDim.x;
    for (int i = tid; i < n; i += nt) g_cnt[i] = 0;
    if (tid < DD) { g_sum[tid] = 0.f; g_sumsq[tid] = 0.f; }
}

// ---------------- h -> fp16 mirror ----------------
__global__ void k_h2h(const float* __restrict__ h, int n) {
    int i = blockIdx.x * blockDim.x + threadIdx.x;
    int total = n * (DD / 4);
    if (i >= total) return;
    float4 v = ((const float4*)h)[i];
    __half2 a = __floats2half2_rn(v.x, v.y);
    __half2 b = __floats2half2_rn(v.z, v.w);
    uint2 u;
    u.x = *(unsigned*)&a;
    u.y = *(unsigned*)&b;
    ((uint2*)g_h16)[i] = u;
}

// ---------------- degree histogram ----------------
__global__ void k_hist(const int* __restrict__ dst, int e, int n) {
    int i = blockIdx.x * blockDim.x + threadIdx.x;
    if (i >= e) return;
    int d = edge_idx(dst, i);
    if ((unsigned)d < (unsigned)n) atomicAdd(&g_cnt[d], 1);
}

// ---------------- decoupled scan ----------------
__global__ void __launch_bounds__(SCAN_B) k_scan1(int n) {
    __shared__ int sdata[SCAN_B];
    int tid = threadIdx.x;
    int i = blockIdx.x * SCAN_B + tid;
    int v = (i < n) ? g_cnt[i] : 0;
    sdata[tid] = v;
    __syncthreads();
    #pragma unroll
    for (int off = 1; off < SCAN_B; off <<= 1) {
        int t = (tid >= off) ? sdata[tid - off] : 0;
        __syncthreads();
        sdata[tid] += t;
        __syncthreads();
    }
    if (i < n) g_off[i + 1] = sdata[tid];
    if (tid == SCAN_B - 1) g_part[blockIdx.x] = sdata[tid];
}

__global__ void __launch_bounds__(MAXPARTS) k_scan2(int nblocks) {
    __shared__ int sdata[MAXPARTS];
    int tid = threadIdx.x;
    int v = (tid < nblocks) ? g_part[tid] : 0;
    sdata[tid] = v;
    __syncthreads();
    #pragma unroll
    for (int off = 1; off < MAXPARTS; off <<= 1) {
        int t = (tid >= off) ? sdata[tid - off] : 0;
        __syncthreads();
        sdata[tid] += t;
        __syncthreads();
    }
    if (tid < nblocks) g_part[tid] = sdata[tid] - v;
}

__global__ void __launch_bounds__(SCAN_B) k_scan3(int n) {
    int i = blockIdx.x * SCAN_B + threadIdx.x;
    if (i >= n) return;
    int carry = g_part[blockIdx.x];
    int incl = g_off[i + 1] + carry;
    g_off[i + 1] = incl;
    g_cur[i] = incl - g_cnt[i];
    if (i == 0) g_off[0] = 0;
}

// ---------------- bucket fill ----------------
__global__ void k_fill(const int* __restrict__ src,
                       const int* __restrict__ dst, int e, int n) {
    int i = blockIdx.x * blockDim.x + threadIdx.x;
    if (i >= e) return;
    int d = edge_idx(dst, i);
    int s = edge_idx(src, i);
    if ((unsigned)d >= (unsigned)n || (unsigned)s >= (unsigned)n) return;
    int pos = atomicAdd(&g_cur[d], 1);
    if ((unsigned)pos < (unsigned)EMAX) g_esrc[pos] = s;
}

// ---------------- warp-per-node gather (fp16 rows) + mean ----------------
__global__ void k_gather(int n) {
    int gw = (blockIdx.x * blockDim.x + threadIdx.x) >> 5;
    int lane = threadIdx.x & 31;
    if (gw >= n) return;
    int o0 = g_off[gw], o1 = g_off[gw + 1];
    const uint2* h2 = (const uint2*)g_h16;   // 4 halves per uint2, 32 per row
    float4 acc = make_float4(0.f, 0.f, 0.f, 0.f);
    for (int jb = o0; jb < o1; jb += 32) {
        int myv = (jb + lane < o1) ? g_esrc[jb + lane] : 0;
        int cnt = min(32, o1 - jb);
        #pragma unroll 4
        for (int k = 0; k < cnt; k++) {
            int s = __shfl_sync(0xffffffffu, myv, k);
            uint2 raw = h2[s * 32 + lane];
            __half2 p0 = *(__half2*)&raw.x;
            __half2 p1 = *(__half2*)&raw.y;
            float2 f0 = __half22float2(p0);
            float2 f1 = __half22float2(p1);
            acc.x += f0.x; acc.y += f0.y; acc.z += f1.x; acc.w += f1.y;
        }
    }
    float inv = 1.0f / fmaxf((float)(o1 - o0), 1.0f);
    acc.x *= inv; acc.y *= inv; acc.z *= inv; acc.w *= inv;
    ((float4*)g_neigh)[gw * 32 + lane] = acc;
}

// ---------------- tf32 tensor-core dual-GEMM + bias + relu + BN sums ----------------
__global__ void __launch_bounds__(256, 1) k_gemm_tc(
    const float* __restrict__ h, const float* __restrict__ Wself,
    const float* __restrict__ Wneigh, const float* __restrict__ bias,
    float* __restrict__ out, int n, int ntiles)
{
    extern __shared__ float sm[];
    float* Ws = sm;                    // 256 * WPITCH
    float* As = sm + 256 * WPITCH;     // MT * APITCH
    int tid = threadIdx.x;
    int wid = tid >> 5, lane = tid & 31;
    int g = lane >> 2, t = lane & 3;
    int wm = wid & 1, wn = wid >> 1;
    int colb = wn * 32;

    // stage W once (tf32-converted)
    {
        int row = tid;
        const float* srcw = (row < DD) ? (Wself + row * DD) : (Wneigh + (row - DD) * DD);
        float* dstRow = Ws + row * WPITCH;
        for (int c = 0; c < DD; c += 4) {
            float4 v = *(const float4*)(srcw + c);
            uint4 uu = make_uint4(f2tf(v.x), f2tf(v.y), f2tf(v.z), f2tf(v.w));
            *(uint4*)(dstRow + c) = uu;
        }
    }

    float bs[4][2];
    #pragma unroll
    for (int j = 0; j < 4; j++) {
        bs[j][0] = bias[colb + j * 8 + 2 * t];
        bs[j][1] = bias[colb + j * 8 + 2 * t + 1];
    }
    float csum[4][2] = {{0.f,0.f},{0.f,0.f},{0.f,0.f},{0.f,0.f}};
    float csq [4][2] = {{0.f,0.f},{0.f,0.f},{0.f,0.f},{0.f,0.f}};

    const unsigned* Asu = (const unsigned*)As;
    const unsigned* Wsu = (const unsigned*)Ws;

    for (int tile = blockIdx.x; tile < ntiles; tile += gridDim.x) {
        int m0 = tile * MT;
        __syncthreads();
        #pragma unroll
        for (int it = 0; it < 16; it++) {
            int f4 = tid + it * 256;
            int row = f4 >> 6, c4 = f4 & 63;
            int rg = m0 + row;
            float4 v = make_float4(0.f, 0.f, 0.f, 0.f);
            if (rg < n)
                v = (c4 < 32) ? ((const float4*)h)[rg * 32 + c4]
                              : ((const float4*)g_neigh)[rg * 32 + c4 - 32];
            uint4 uu = make_uint4(f2tf(v.x), f2tf(v.y), f2tf(v.z), f2tf(v.w));
            *(uint4*)(As + row * APITCH + c4 * 4) = uu;
        }
        __syncthreads();

        float acc[2][4][4];
        #pragma unroll
        for (int i = 0; i < 2; i++)
            #pragma unroll
            for (int j = 0; j < 4; j++)
                #pragma unroll
                for (int q = 0; q < 4; q++) acc[i][j][q] = 0.f;

        #pragma unroll 4
        for (int kc = 0; kc < 32; kc++) {
            int k0 = kc * 8;
            unsigned a[2][4];
            #pragma unroll
            for (int i = 0; i < 2; i++) {
                int rb = (wm * 32 + i * 16 + g) * APITCH + k0 + t;
                a[i][0] = Asu[rb];
                a[i][1] = Asu[rb + 8 * APITCH];
                a[i][2] = Asu[rb + 4];
                a[i][3] = Asu[rb + 8 * APITCH + 4];
            }
            #pragma unroll
            for (int j = 0; j < 4; j++) {
                int ba = (k0 + t) * WPITCH + colb + j * 8 + g;
                unsigned b0 = Wsu[ba];
                unsigned b1 = Wsu[ba + 4 * WPITCH];
                mma_tf32(acc[0][j], a[0], b0, b1);
                mma_tf32(acc[1][j], a[1], b0, b1);
            }
        }

        #pragma unroll
        for (int i = 0; i < 2; i++) {
            int row0 = m0 + wm * 32 + i * 16 + g;
            #pragma unroll
            for (int j = 0; j < 4; j++) {
                int col = colb + j * 8 + 2 * t;
                float c0 = fmaxf(acc[i][j][0] + bs[j][0], 0.f);
                float c1 = fmaxf(acc[i][j][1] + bs[j][1], 0.f);
                float c2 = fmaxf(acc[i][j][2] + bs[j][0], 0.f);
                float c3 = fmaxf(acc[i][j][3] + bs[j][1], 0.f);
                if (row0 < n) {
                    *(float2*)&out[(size_t)row0 * DD + col] = make_float2(c0, c1);
                    csum[j][0] += c0; csq[j][0] += c0 * c0;
                    csum[j][1] += c1; csq[j][1] += c1 * c1;
                }
                if (row0 + 8 < n) {
                    *(float2*)&out[(size_t)(row0 + 8) * DD + col] = make_float2(c2, c3);
                    csum[j][0] += c2; csq[j][0] += c2 * c2;
                    csum[j][1] += c3; csq[j][1] += c3 * c3;
                }
            }
        }
    }

    #pragma unroll
    for (int j = 0; j < 4; j++)
        #pragma unroll
        for (int p = 0; p < 2; p++) {
            float s = csum[j][p], q = csq[j][p];
            #pragma unroll
            for (int off = 16; off >= 4; off >>= 1) {
                s += __shfl_down_sync(0xffffffffu, s, off);
                q += __shfl_down_sync(0xffffffffu, q, off);
            }
            if (g == 0) {
                int col = colb + j * 8 + 2 * t + p;
                atomicAdd(&g_sum[col], s);
                atomicAdd(&g_sumsq[col], q);
            }
        }
}

// ---------------- normalize + residual (stats computed inline) ----------------
__global__ void k_final(const float* __restrict__ h, const float* __restrict__ gamma,
                        const float* __restrict__ beta, float* __restrict__ out,
                        int n, float inv_n) {
    int i = blockIdx.x * blockDim.x + threadIdx.x;
    int total = n * (DD / 4);
    if (i >= total) return;
    int j4 = i & 31;
    float4 su = ((const float4*)g_sum)[j4];
    float4 sq = ((const float4*)g_sumsq)[j4];
    float4 mu, rs;
    mu.x = su.x * inv_n; mu.y = su.y * inv_n; mu.z = su.z * inv_n; mu.w = su.w * inv_n;
    rs.x = rsqrtf(sq.x * inv_n - mu.x * mu.x + EPS);
    rs.y = rsqrtf(sq.y * inv_n - mu.y * mu.y + EPS);
    rs.z = rsqrtf(sq.z * inv_n - mu.z * mu.z + EPS);
    rs.w = rsqrtf(sq.w * inv_n - mu.w * mu.w + EPS);
    float4 v  = ((float4*)out)[i];
    float4 hv = ((const float4*)h)[i];
    float4 ga = ((const float4*)gamma)[j4];
    float4 be = ((const float4*)beta)[j4];
    v.x = hv.x + (v.x - mu.x) * rs.x * ga.x + be.x;
    v.y = hv.y + (v.y - mu.y) * rs.y * ga.y + be.y;
    v.z = hv.z + (v.z - mu.z) * rs.z * ga.z + be.z;
    v.w = hv.w + (v.w - mu.w) * rs.w * ga.w + be.w;
    ((float4*)out)[i] = v;
}

// ---------------- launch ----------------
extern "C" void kernel_launch(void* const* d_in, const int* in_sizes, int n_in,
                              void* d_out, int out_size) {
    const float* h     = (const float*)d_in[0];
    const int*   src   = (const int*)d_in[1];
    const int*   dst   = (const int*)d_in[2];
    const float* Wself = (const float*)d_in[3];
    const float* Wneigh= (const float*)d_in[4];
    const float* bias  = (const float*)d_in[5];
    const float* gamma = (const float*)d_in[6];
    const float* beta  = (const float*)d_in[7];
    float* out = (float*)d_out;
    int n = in_sizes[0] / DD;
    int e = in_sizes[1];

    int nscan = (n + SCAN_B - 1) / SCAN_B;

    k_detect<<<1, 32>>>(src, dst, e);
    k_zero<<<512, 256>>>(n);
    k_h2h<<<(n * (DD / 4) + 255) / 256, 256>>>(h, n);
    k_hist<<<(e + 255) / 256, 256>>>(dst, e, n);
    k_scan1<<<nscan, SCAN_B>>>(n);
    k_scan2<<<1, MAXPARTS>>>(nscan);
    k_scan3<<<nscan, SCAN_B>>>(n);
    k_fill<<<(e + 255) / 256, 256>>>(src, dst, e, n);
    k_gather<<<(n * 32 + 255) / 256, 256>>>(n);

    int ntiles = (n + MT - 1) / MT;
    size_t smem = (size_t)(256 * WPITCH + MT * APITCH) * sizeof(float);
    cudaFuncSetAttribute(k_gemm_tc, cudaFuncAttributeMaxDynamicSharedMemorySize, (int)smem);
    k_gemm_tc<<<NSM, 256, smem>>>(h, Wself, Wneigh, bias, out, n, ntiles);

    k_final<<<(n * (DD / 4) + 255) / 256, 256>>>(h, gamma, beta, out, n, 1.0f / (float)n);
}

// round 8
// speedup vs baseline: 1.7846x; 1.0034x over previous
#include <cuda_runtime.h>
#include <cuda_fp16.h>
#include <cstdint>

#define DD 128
#define NMAX 100000
#define EMAX 3200000
#define EPS 1e-5f
#define SCAN_B 1024
#define MAXPARTS 128
#define NSM 148
#define MT 64          // rows per GEMM tile
#define WPITCH 136     // Ws pitch (floats)
#define APITCH 260     // As pitch (floats)

// ---------------- scratch (no cudaMalloc allowed) ----------------
__device__ __align__(16) float g_neigh[(size_t)NMAX * DD];
__device__ __align__(16) __half g_h16[(size_t)NMAX * DD];
__device__ int g_esrc[EMAX];
__device__ int g_cnt[NMAX];
__device__ int g_off[NMAX + 1];
__device__ int g_cur[NMAX];
__device__ int g_part[MAXPARTS];
__device__ float g_sum[DD];
__device__ float g_sumsq[DD];
__device__ int g_is64;

__device__ __forceinline__ int edge_idx(const int* __restrict__ p, int i) {
    return g_is64 ? p[2 * i] : p[i];
}

__device__ __forceinline__ unsigned f2tf(float f) {
    unsigned u; asm("cvt.rna.tf32.f32 %0, %1;" : "=r"(u) : "f"(f)); return u;
}

__device__ __forceinline__ void mma_tf32(float* c, const unsigned* a, unsigned b0, unsigned b1) {
    asm volatile("mma.sync.aligned.m16n8k8.row.col.f32.tf32.tf32.f32 "
                 "{%0,%1,%2,%3}, {%4,%5,%6,%7}, {%8,%9}, {%0,%1,%2,%3};"
                 : "+f"(c[0]), "+f"(c[1]), "+f"(c[2]), "+f"(c[3])
                 : "r"(a[0]), "r"(a[1]), "r"(a[2]), "r"(a[3]), "r"(b0), "r"(b1));
}

// ---------------- dtype probe ----------------
__global__ void k_detect(const int* __restrict__ s, const int* __restrict__ d, int e) {
    if (threadIdx.x == 0 && blockIdx.x == 0) {
        int m = e < 64 ? e : 64;
        int odd = 0;
        for (int i = 0; i < m; i++) odd |= s[2 * i + 1] | d[2 * i + 1];
        g_is64 = (odd == 0) ? 1 : 0;
    }
}

// ---------------- zero counters + h -> fp16 mirror (fused) ----------------
__global__ void k_h2h(const float* __restrict__ h, int n) {
    int tid = blockIdx.x * blockDim.x + threadIdx.x;
    int nt = gridDim.x * blockDim.x;
    int total = n * (DD / 4);
    for (int i = tid; i < total; i += nt) {
        float4 v = ((const float4*)h)[i];
        __half2 a = __floats2half2_rn(v.x, v.y);
        __half2 b = __floats2half2_rn(v.z, v.w);
        uint2 u;
        u.x = *(unsigned*)&a;
        u.y = *(unsigned*)&b;
        ((uint2*)g_h16)[i] = u;
    }
    for (int i = tid; i < n; i += nt) g_cnt[i] = 0;
    if (tid < DD) { g_sum[tid] = 0.f; g_sumsq[tid] = 0.f; }
}

// ---------------- degree histogram ----------------
__global__ void k_hist(const int* __restrict__ dst, int e, int n) {
    int i = blockIdx.x * blockDim.x + threadIdx.x;
    if (i >= e) return;
    int d = edge_idx(dst, i);
    if ((unsigned)d < (unsigned)n) atomicAdd(&g_cnt[d], 1);
}

// ---------------- decoupled scan ----------------
__global__ void __launch_bounds__(SCAN_B) k_scan1(int n) {
    __shared__ int sdata[SCAN_B];
    int tid = threadIdx.x;
    int i = blockIdx.x * SCAN_B + tid;
    int v = (i < n) ? g_cnt[i] : 0;
    sdata[tid] = v;
    __syncthreads();
    #pragma unroll
    for (int off = 1; off < SCAN_B; off <<= 1) {
        int t = (tid >= off) ? sdata[tid - off] : 0;
        __syncthreads();
        sdata[tid] += t;
        __syncthreads();
    }
    if (i < n) g_off[i + 1] = sdata[tid];
    if (tid == SCAN_B - 1) g_part[blockIdx.x] = sdata[tid];
}

__global__ void __launch_bounds__(MAXPARTS) k_scan2(int nblocks) {
    __shared__ int sdata[MAXPARTS];
    int tid = threadIdx.x;
    int v = (tid < nblocks) ? g_part[tid] : 0;
    sdata[tid] = v;
    __syncthreads();
    #pragma unroll
    for (int off = 1; off < MAXPARTS; off <<= 1) {
        int t = (tid >= off) ? sdata[tid - off] : 0;
        __syncthreads();
        sdata[tid] += t;
        __syncthreads();
    }
    if (tid < nblocks) g_part[tid] = sdata[tid] - v;
}

__global__ void __launch_bounds__(SCAN_B) k_scan3(int n) {
    int i = blockIdx.x * SCAN_B + threadIdx.x;
    if (i >= n) return;
    int carry = g_part[blockIdx.x];
    int incl = g_off[i + 1] + carry;
    g_off[i + 1] = incl;
    g_cur[i] = incl - g_cnt[i];
    if (i == 0) g_off[0] = 0;
}

// ---------------- bucket fill ----------------
__global__ void k_fill(const int* __restrict__ src,
                       const int* __restrict__ dst, int e, int n) {
    int i = blockIdx.x * blockDim.x + threadIdx.x;
    if (i >= e) return;
    int d = edge_idx(dst, i);
    int s = edge_idx(src, i);
    if ((unsigned)d >= (unsigned)n || (unsigned)s >= (unsigned)n) return;
    int pos = atomicAdd(&g_cur[d], 1);
    if ((unsigned)pos < (unsigned)EMAX) g_esrc[pos] = s;
}

// ---------------- warp-per-node gather, high-MLP (2 edges/iter, LDG.128) ------
__global__ void k_gather(int n) {
    int gw = (blockIdx.x * blockDim.x + threadIdx.x) >> 5;
    int lane = threadIdx.x & 31;
    if (gw >= n) return;
    int o0 = g_off[gw], o1 = g_off[gw + 1];
    int lane16 = lane & 15, half = lane >> 4;
    const uint4* h4 = (const uint4*)g_h16;   // 16B = 8 halves; 16 uint4 per row
    float acc[8];
    #pragma unroll
    for (int j = 0; j < 8; j++) acc[j] = 0.f;

    for (int jb = o0; jb < o1; jb += 32) {
        int myv = (jb + lane < o1) ? g_esrc[jb + lane] : 0;
        int cnt = min(32, o1 - jb);
        int k = 0;
        #pragma unroll 8
        for (; k + 2 <= cnt; k += 2) {
            int s = __shfl_sync(0xffffffffu, myv, k + half);
            uint4 raw = h4[s * 16 + lane16];
            const __half2* hp = (const __half2*)&raw;
            #pragma unroll
            for (int q = 0; q < 4; q++) {
                float2 f = __half22float2(hp[q]);
                acc[2 * q]     += f.x;
                acc[2 * q + 1] += f.y;
            }
        }
        if (k < cnt) {   // odd leftover edge: processed by half 0 only
            int s = __shfl_sync(0xffffffffu, myv, k);
            if (half == 0) {
                uint4 raw = h4[s * 16 + lane16];
                const __half2* hp = (const __half2*)&raw;
                #pragma unroll
                for (int q = 0; q < 4; q++) {
                    float2 f = __half22float2(hp[q]);
                    acc[2 * q]     += f.x;
                    acc[2 * q + 1] += f.y;
                }
            }
        }
    }

    // combine the two half-warp partial sums
    #pragma unroll
    for (int j = 0; j < 8; j++)
        acc[j] += __shfl_xor_sync(0xffffffffu, acc[j], 16);

    if (half == 0) {
        float inv = 1.0f / fmaxf((float)(o1 - o0), 1.0f);
        float4* dst = (float4*)(g_neigh + (size_t)gw * DD + lane16 * 8);
        dst[0] = make_float4(acc[0] * inv, acc[1] * inv, acc[2] * inv, acc[3] * inv);
        dst[1] = make_float4(acc[4] * inv, acc[5] * inv, acc[6] * inv, acc[7] * inv);
    }
}

// ---------------- tf32 tensor-core dual-GEMM + bias + relu + BN sums ----------------
__global__ void __launch_bounds__(256, 1) k_gemm_tc(
    const float* __restrict__ h, const float* __restrict__ Wself,
    const float* __restrict__ Wneigh, const float* __restrict__ bias,
    float* __restrict__ out, int n, int ntiles)
{
    extern __shared__ float sm[];
    float* Ws = sm;                    // 256 * WPITCH
    float* As = sm + 256 * WPITCH;     // MT * APITCH
    int tid = threadIdx.x;
    int wid = tid >> 5, lane = tid & 31;
    int g = lane >> 2, t = lane & 3;
    int wm = wid & 1, wn = wid >> 1;
    int colb = wn * 32;

    {
        int row = tid;
        const float* srcw = (row < DD) ? (Wself + row * DD) : (Wneigh + (row - DD) * DD);
        float* dstRow = Ws + row * WPITCH;
        for (int c = 0; c < DD; c += 4) {
            float4 v = *(const float4*)(srcw + c);
            uint4 uu = make_uint4(f2tf(v.x), f2tf(v.y), f2tf(v.z), f2tf(v.w));
            *(uint4*)(dstRow + c) = uu;
        }
    }

    float bs[4][2];
    #pragma unroll
    for (int j = 0; j < 4; j++) {
        bs[j][0] = bias[colb + j * 8 + 2 * t];
        bs[j][1] = bias[colb + j * 8 + 2 * t + 1];
    }
    float csum[4][2] = {{0.f,0.f},{0.f,0.f},{0.f,0.f},{0.f,0.f}};
    float csq [4][2] = {{0.f,0.f},{0.f,0.f},{0.f,0.f},{0.f,0.f}};

    const unsigned* Asu = (const unsigned*)As;
    const unsigned* Wsu = (const unsigned*)Ws;

    for (int tile = blockIdx.x; tile < ntiles; tile += gridDim.x) {
        int m0 = tile * MT;
        __syncthreads();
        #pragma unroll
        for (int it = 0; it < 16; it++) {
            int f4 = tid + it * 256;
            int row = f4 >> 6, c4 = f4 & 63;
            int rg = m0 + row;
            float4 v = make_float4(0.f, 0.f, 0.f, 0.f);
            if (rg < n)
                v = (c4 < 32) ? ((const float4*)h)[rg * 32 + c4]
                              : ((const float4*)g_neigh)[rg * 32 + c4 - 32];
            uint4 uu = make_uint4(f2tf(v.x), f2tf(v.y), f2tf(v.z), f2tf(v.w));
            *(uint4*)(As + row * APITCH + c4 * 4) = uu;
        }
        __syncthreads();

        float acc[2][4][4];
        #pragma unroll
        for (int i = 0; i < 2; i++)
            #pragma unroll
            for (int j = 0; j < 4; j++)
                #pragma unroll
                for (int q = 0; q < 4; q++) acc[i][j][q] = 0.f;

        #pragma unroll 4
        for (int kc = 0; kc < 32; kc++) {
            int k0 = kc * 8;
            unsigned a[2][4];
            #pragma unroll
            for (int i = 0; i < 2; i++) {
                int rb = (wm * 32 + i * 16 + g) * APITCH + k0 + t;
                a[i][0] = Asu[rb];
                a[i][1] = Asu[rb + 8 * APITCH];
                a[i][2] = Asu[rb + 4];
                a[i][3] = Asu[rb + 8 * APITCH + 4];
            }
            #pragma unroll
            for (int j = 0; j < 4; j++) {
                int ba = (k0 + t) * WPITCH + colb + j * 8 + g;
                unsigned b0 = Wsu[ba];
                unsigned b1 = Wsu[ba + 4 * WPITCH];
                mma_tf32(acc[0][j], a[0], b0, b1);
                mma_tf32(acc[1][j], a[1], b0, b1);
            }
        }

        #pragma unroll
        for (int i = 0; i < 2; i++) {
            int row0 = m0 + wm * 32 + i * 16 + g;
            #pragma unroll
            for (int j = 0; j < 4; j++) {
                int col = colb + j * 8 + 2 * t;
                float c0 = fmaxf(acc[i][j][0] + bs[j][0], 0.f);
                float c1 = fmaxf(acc[i][j][1] + bs[j][1], 0.f);
                float c2 = fmaxf(acc[i][j][2] + bs[j][0], 0.f);
                float c3 = fmaxf(acc[i][j][3] + bs[j][1], 0.f);
                if (row0 < n) {
                    *(float2*)&out[(size_t)row0 * DD + col] = make_float2(c0, c1);
                    csum[j][0] += c0; csq[j][0] += c0 * c0;
                    csum[j][1] += c1; csq[j][1] += c1 * c1;
                }
                if (row0 + 8 < n) {
                    *(float2*)&out[(size_t)(row0 + 8) * DD + col] = make_float2(c2, c3);
                    csum[j][0] += c2; csq[j][0] += c2 * c2;
                    csum[j][1] += c3; csq[j][1] += c3 * c3;
                }
            }
        }
    }

    #pragma unroll
    for (int j = 0; j < 4; j++)
        #pragma unroll
        for (int p = 0; p < 2; p++) {
            float s = csum[j][p], q = csq[j][p];
            #pragma unroll
            for (int off = 16; off >= 4; off >>= 1) {
                s += __shfl_down_sync(0xffffffffu, s, off);
                q += __shfl_down_sync(0xffffffffu, q, off);
            }
            if (g == 0) {
                int col = colb + j * 8 + 2 * t + p;
                atomicAdd(&g_sum[col], s);
                atomicAdd(&g_sumsq[col], q);
            }
        }
}

// ---------------- normalize + residual (stats computed inline) ----------------
__global__ void k_final(const float* __restrict__ h, const float* __restrict__ gamma,
                        const float* __restrict__ beta, float* __restrict__ out,
                        int n, float inv_n) {
    int i = blockIdx.x * blockDim.x + threadIdx.x;
    int total = n * (DD / 4);
    if (i >= total) return;
    int j4 = i & 31;
    float4 su = ((const float4*)g_sum)[j4];
    float4 sq = ((const float4*)g_sumsq)[j4];
    float4 mu, rs;
    mu.x = su.x * inv_n; mu.y = su.y * inv_n; mu.z = su.z * inv_n; mu.w = su.w * inv_n;
    rs.x = rsqrtf(sq.x * inv_n - mu.x * mu.x + EPS);
    rs.y = rsqrtf(sq.y * inv_n - mu.y * mu.y + EPS);
    rs.z = rsqrtf(sq.z * inv_n - mu.z * mu.z + EPS);
    rs.w = rsqrtf(sq.w * inv_n - mu.w * mu.w + EPS);
    float4 v  = ((float4*)out)[i];
    float4 hv = ((const float4*)h)[i];
    float4 ga = ((const float4*)gamma)[j4];
    float4 be = ((const float4*)beta)[j4];
    v.x = hv.x + (v.x - mu.x) * rs.x * ga.x + be.x;
    v.y = hv.y + (v.y - mu.y) * rs.y * ga.y + be.y;
    v.z = hv.z + (v.z - mu.z) * rs.z * ga.z + be.z;
    v.w = hv.w + (v.w - mu.w) * rs.w * ga.w + be.w;
    ((float4*)out)[i] = v;
}

// ---------------- launch ----------------
extern "C" void kernel_launch(void* const* d_in, const int* in_sizes, int n_in,
                              void* d_out, int out_size) {
    const float* h     = (const float*)d_in[0];
    const int*   src   = (const int*)d_in[1];
    const int*   dst   = (const int*)d_in[2];
    const float* Wself = (const float*)d_in[3];
    const float* Wneigh= (const float*)d_in[4];
    const float* bias  = (const float*)d_in[5];
    const float* gamma = (const float*)d_in[6];
    const float* beta  = (const float*)d_in[7];
    float* out = (float*)d_out;
    int n = in_sizes[0] / DD;
    int e = in_sizes[1];

    int nscan = (n + SCAN_B - 1) / SCAN_B;

    k_detect<<<1, 32>>>(src, dst, e);
    k_h2h<<<1024, 256>>>(h, n);
    k_hist<<<(e + 255) / 256, 256>>>(dst, e, n);
    k_scan1<<<nscan, SCAN_B>>>(n);
    k_scan2<<<1, MAXPARTS>>>(nscan);
    k_scan3<<<nscan, SCAN_B>>>(n);
    k_fill<<<(e + 255) / 256, 256>>>(src, dst, e, n);
    k_gather<<<(n * 32 + 255) / 256, 256>>>(n);

    int ntiles = (n + MT - 1) / MT;
    size_t smem = (size_t)(256 * WPITCH + MT * APITCH) * sizeof(float);
    cudaFuncSetAttribute(k_gemm_tc, cudaFuncAttributeMaxDynamicSharedMemorySize, (int)smem);
    k_gemm_tc<<<NSM, 256, smem>>>(h, Wself, Wneigh, bias, out, n, ntiles);

    k_final<<<(n * (DD / 4) + 255) / 256, 256>>>(h, gamma, beta, out, n, 1.0f / (float)n);
}

// round 11
// speedup vs baseline: 2.3347x; 1.3083x over previous
#include <cuda_runtime.h>
#include <cuda_fp16.h>
#include <cstdint>

#define DD 128
#define NMAX 100000
#define EMAX 3200000
#define EPS 1e-5f
#define SCAN_B 1024
#define MAXPARTS 128
#define NSM 148
#define MT 64          // rows per GEMM tile
#define WP16 136       // Ws pitch in uints (half2): 8t+g bank pattern
#define AP16 132       // As pitch in uints (half2): 4g+t bank pattern

// ---------------- scratch (no cudaMalloc allowed) ----------------
__device__ __align__(16) __half g_h16[(size_t)NMAX * DD];
__device__ __align__(16) __half g_n16[(size_t)NMAX * DD];
__device__ int g_esrc[EMAX];
__device__ int g_cnt[NMAX];
__device__ int g_off[NMAX + 1];
__device__ int g_cur[NMAX];
__device__ int g_part[MAXPARTS];
__device__ float g_sum[DD];
__device__ float g_sumsq[DD];
__device__ int g_is64;

__device__ __forceinline__ int edge_idx(const int* __restrict__ p, int i) {
    return g_is64 ? p[2 * i] : p[i];
}

__device__ __forceinline__ void mma_f16(float* c, const unsigned* a, unsigned b0, unsigned b1) {
    asm volatile("mma.sync.aligned.m16n8k16.row.col.f32.f16.f16.f32 "
                 "{%0,%1,%2,%3}, {%4,%5,%6,%7}, {%8,%9}, {%0,%1,%2,%3};"
                 : "+f"(c[0]), "+f"(c[1]), "+f"(c[2]), "+f"(c[3])
                 : "r"(a[0]), "r"(a[1]), "r"(a[2]), "r"(a[3]), "r"(b0), "r"(b1));
}

// ---------------- dtype probe ----------------
__global__ void k_detect(const int* __restrict__ s, const int* __restrict__ d, int e) {
    if (threadIdx.x == 0 && blockIdx.x == 0) {
        int m = e < 64 ? e : 64;
        int odd = 0;
        for (int i = 0; i < m; i++) odd |= s[2 * i + 1] | d[2 * i + 1];
        g_is64 = (odd == 0) ? 1 : 0;
    }
}

// ---------------- zero counters + h -> fp16 mirror (fused) ----------------
__global__ void k_h2h(const float* __restrict__ h, int n) {
    int tid = blockIdx.x * blockDim.x + threadIdx.x;
    int nt = gridDim.x * blockDim.x;
    int total = n * (DD / 4);
    for (int i = tid; i < total; i += nt) {
        float4 v = ((const float4*)h)[i];
        __half2 a = __floats2half2_rn(v.x, v.y);
        __half2 b = __floats2half2_rn(v.z, v.w);
        uint2 u;
        u.x = *(unsigned*)&a;
        u.y = *(unsigned*)&b;
        ((uint2*)g_h16)[i] = u;
    }
    for (int i = tid; i < n; i += nt) g_cnt[i] = 0;
    if (tid < DD) { g_sum[tid] = 0.f; g_sumsq[tid] = 0.f; }
}

// ---------------- degree histogram ----------------
__global__ void k_hist(const int* __restrict__ dst, int e, int n) {
    int i = blockIdx.x * blockDim.x + threadIdx.x;
    if (i >= e) return;
    int d = edge_idx(dst, i);
    if ((unsigned)d < (unsigned)n) atomicAdd(&g_cnt[d], 1);
}

// ---------------- decoupled scan ----------------
__global__ void __launch_bounds__(SCAN_B) k_scan1(int n) {
    __shared__ int sdata[SCAN_B];
    int tid = threadIdx.x;
    int i = blockIdx.x * SCAN_B + tid;
    int v = (i < n) ? g_cnt[i] : 0;
    sdata[tid] = v;
    __syncthreads();
    #pragma unroll
    for (int off = 1; off < SCAN_B; off <<= 1) {
        int t = (tid >= off) ? sdata[tid - off] : 0;
        __syncthreads();
        sdata[tid] += t;
        __syncthreads();
    }
    if (i < n) g_off[i + 1] = sdata[tid];
    if (tid == SCAN_B - 1) g_part[blockIdx.x] = sdata[tid];
}

__global__ void __launch_bounds__(MAXPARTS) k_scan2(int nblocks) {
    __shared__ int sdata[MAXPARTS];
    int tid = threadIdx.x;
    int v = (tid < nblocks) ? g_part[tid] : 0;
    sdata[tid] = v;
    __syncthreads();
    #pragma unroll
    for (int off = 1; off < MAXPARTS; off <<= 1) {
        int t = (tid >= off) ? sdata[tid - off] : 0;
        __syncthreads();
        sdata[tid] += t;
        __syncthreads();
    }
    if (tid < nblocks) g_part[tid] = sdata[tid] - v;
}

__global__ void __launch_bounds__(SCAN_B) k_scan3(int n) {
    int i = blockIdx.x * SCAN_B + threadIdx.x;
    if (i >= n) return;
    int carry = g_part[blockIdx.x];
    int incl = g_off[i + 1] + carry;
    g_off[i + 1] = incl;
    g_cur[i] = incl - g_cnt[i];
    if (i == 0) g_off[0] = 0;
}

// ---------------- bucket fill ----------------
__global__ void k_fill(const int* __restrict__ src,
                       const int* __restrict__ dst, int e, int n) {
    int i = blockIdx.x * blockDim.x + threadIdx.x;
    if (i >= e) return;
    int d = edge_idx(dst, i);
    int s = edge_idx(src, i);
    if ((unsigned)d >= (unsigned)n || (unsigned)s >= (unsigned)n) return;
    int pos = atomicAdd(&g_cur[d], 1);
    if ((unsigned)pos < (unsigned)EMAX) g_esrc[pos] = s;
}

// ---------------- warp-per-node gather (fp16 rows) -> fp16 neigh ----------------
__global__ void k_gather(int n) {
    int gw = (blockIdx.x * blockDim.x + threadIdx.x) >> 5;
    int lane = threadIdx.x & 31;
    if (gw >= n) return;
    int o0 = g_off[gw], o1 = g_off[gw + 1];
    int lane16 = lane & 15, half = lane >> 4;
    const uint4* h4 = (const uint4*)g_h16;   // 16B = 8 halves; 16 uint4 per row
    float acc[8];
    #pragma unroll
    for (int j = 0; j < 8; j++) acc[j] = 0.f;

    for (int jb = o0; jb < o1; jb += 32) {
        int myv = (jb + lane < o1) ? g_esrc[jb + lane] : 0;
        int cnt = min(32, o1 - jb);
        int k = 0;
        #pragma unroll 8
        for (; k + 2 <= cnt; k += 2) {
            int s = __shfl_sync(0xffffffffu, myv, k + half);
            uint4 raw = h4[s * 16 + lane16];
            const __half2* hp = (const __half2*)&raw;
            #pragma unroll
            for (int q = 0; q < 4; q++) {
                float2 f = __half22float2(hp[q]);
                acc[2 * q]     += f.x;
                acc[2 * q + 1] += f.y;
            }
        }
        if (k < cnt) {
            int s = __shfl_sync(0xffffffffu, myv, k);
            if (half == 0) {
                uint4 raw = h4[s * 16 + lane16];
                const __half2* hp = (const __half2*)&raw;
                #pragma unroll
                for (int q = 0; q < 4; q++) {
                    float2 f = __half22float2(hp[q]);
                    acc[2 * q]     += f.x;
                    acc[2 * q + 1] += f.y;
                }
            }
        }
    }

    #pragma unroll
    for (int j = 0; j < 8; j++)
        acc[j] += __shfl_xor_sync(0xffffffffu, acc[j], 16);

    if (half == 0) {
        float inv = 1.0f / fmaxf((float)(o1 - o0), 1.0f);
        uint4 o;
        __half2 p0 = __floats2half2_rn(acc[0] * inv, acc[1] * inv);
        __half2 p1 = __floats2half2_rn(acc[2] * inv, acc[3] * inv);
        __half2 p2 = __floats2half2_rn(acc[4] * inv, acc[5] * inv);
        __half2 p3 = __floats2half2_rn(acc[6] * inv, acc[7] * inv);
        o.x = *(unsigned*)&p0; o.y = *(unsigned*)&p1;
        o.z = *(unsigned*)&p2; o.w = *(unsigned*)&p3;
        ((uint4*)g_n16)[gw * 16 + lane16] = o;
    }
}

// ---------------- fp16 tensor-core dual-GEMM + bias + relu + BN sums ----------------
// A = [h16 | n16] (K=256 halves), W staged as half2 K-pairs: Ws16u[k2][col].
// 8 warps = 2(m) x 4(n); warp tile 32x32 via mma.m16n8k16 f16.f32.
__global__ void __launch_bounds__(256, 1) k_gemm_tc(
    const float* __restrict__ Wself, const float* __restrict__ Wneigh,
    const float* __restrict__ bias, float* __restrict__ out, int n, int ntiles)
{
    extern __shared__ unsigned smu[];
    unsigned* Wsu = smu;                 // 128 * WP16 uints (half2)
    unsigned* Asu = smu + 128 * WP16;    // MT * AP16 uints (half2)
    int tid = threadIdx.x;
    int wid = tid >> 5, lane = tid & 31;
    int g = lane >> 2, t = lane & 3;
    int wm = wid & 1, wn = wid >> 1;
    int colb = wn * 32;

    // stage W once: Ws16u[k2*WP16 + col] = half2(W[2k2][col], W[2k2+1][col])
    for (int i = tid; i < 128 * DD; i += 256) {
        int k2 = i >> 7, col = i & 127;
        int k = 2 * k2;
        const float* w0 = (k < DD) ? (Wself + k * DD) : (Wneigh + (k - DD) * DD);
        const float* w1 = w0 + DD;   // k+1 row, same matrix (k even -> same side)
        __half2 p = __floats2half2_rn(w0[col], w1[col]);
        Wsu[k2 * WP16 + col] = *(unsigned*)&p;
    }

    float bs[4][2];
    #pragma unroll
    for (int j = 0; j < 4; j++) {
        bs[j][0] = bias[colb + j * 8 + 2 * t];
        bs[j][1] = bias[colb + j * 8 + 2 * t + 1];
    }
    float csum[4][2] = {{0.f,0.f},{0.f,0.f},{0.f,0.f},{0.f,0.f}};
    float csq [4][2] = {{0.f,0.f},{0.f,0.f},{0.f,0.f},{0.f,0.f}};

    const uint4* h4 = (const uint4*)g_h16;   // 16 uint4 per row
    const uint4* n4 = (const uint4*)g_n16;

    for (int tile = blockIdx.x; tile < ntiles; tile += gridDim.x) {
        int m0 = tile * MT;
        __syncthreads();
        // stage A tile: row-major half2, [0:64) h16, [64:128) n16  (pure copies)
        #pragma unroll
        for (int it = 0; it < 8; it++) {
            int q = tid + it * 256;          // MT*32 = 2048 uint4
            int row = q >> 5, c4 = q & 31;   // c4: 0..31 uint4 per row
            int rg = m0 + row;
            uint4 v = make_uint4(0u, 0u, 0u, 0u);
            if (rg < n)
                v = (c4 < 16) ? h4[rg * 16 + c4] : n4[rg * 16 + (c4 - 16)];
            *(uint4*)&Asu[row * AP16 + c4 * 4] = v;
        }
        __syncthreads();

        float acc[2][4][4];
        #pragma unroll
        for (int i = 0; i < 2; i++)
            #pragma unroll
            for (int j = 0; j < 4; j++)
                #pragma unroll
                for (int q = 0; q < 4; q++) acc[i][j][q] = 0.f;

        #pragma unroll 4
        for (int kc = 0; kc < 16; kc++) {       // 16 k-steps of K=16
            int k2b = kc * 8;                   // k2 base (half2 units)
            unsigned a[2][4];
            #pragma unroll
            for (int i = 0; i < 2; i++) {
                int rb = (wm * 32 + i * 16 + g) * AP16 + k2b + t;
                a[i][0] = Asu[rb];
                a[i][1] = Asu[rb + 8 * AP16];
                a[i][2] = Asu[rb + 4];
                a[i][3] = Asu[rb + 8 * AP16 + 4];
            }
            #pragma unroll
            for (int j = 0; j < 4; j++) {
                int col = colb + j * 8 + g;
                unsigned b0 = Wsu[(k2b + t) * WP16 + col];
                unsigned b1 = Wsu[(k2b + 4 + t) * WP16 + col];
                mma_f16(acc[0][j], a[0], b0, b1);
                mma_f16(acc[1][j], a[1], b0, b1);
            }
        }

        #pragma unroll
        for (int i = 0; i < 2; i++) {
            int row0 = m0 + wm * 32 + i * 16 + g;
            #pragma unroll
            for (int j = 0; j < 4; j++) {
                int col = colb + j * 8 + 2 * t;
                float c0 = fmaxf(acc[i][j][0] + bs[j][0], 0.f);
                float c1 = fmaxf(acc[i][j][1] + bs[j][1], 0.f);
                float c2 = fmaxf(acc[i][j][2] + bs[j][0], 0.f);
                float c3 = fmaxf(acc[i][j][3] + bs[j][1], 0.f);
                if (row0 < n) {
                    *(float2*)&out[(size_t)row0 * DD + col] = make_float2(c0, c1);
                    csum[j][0] += c0; csq[j][0] += c0 * c0;
                    csum[j][1] += c1; csq[j][1] += c1 * c1;
                }
                if (row0 + 8 < n) {
                    *(float2*)&out[(size_t)(row0 + 8) * DD + col] = make_float2(c2, c3);
                    csum[j][0] += c2; csq[j][0] += c2 * c2;
                    csum[j][1] += c3; csq[j][1] += c3 * c3;
                }
            }
        }
    }

    #pragma unroll
    for (int j = 0; j < 4; j++)
        #pragma unroll
        for (int p = 0; p < 2; p++) {
            float s = csum[j][p], q = csq[j][p];
            #pragma unroll
            for (int off = 16; off >= 4; off >>= 1) {
                s += __shfl_down_sync(0xffffffffu, s, off);
                q += __shfl_down_sync(0xffffffffu, q, off);
            }
            if (g == 0) {
                int col = colb + j * 8 + 2 * t + p;
                atomicAdd(&g_sum[col], s);
                atomicAdd(&g_sumsq[col], q);
            }
        }
}

// ---------------- normalize + residual (stats computed inline) ----------------
__global__ void k_final(const float* __restrict__ h, const float* __restrict__ gamma,
                        const float* __restrict__ beta, float* __restrict__ out,
                        int n, float inv_n) {
    int i = blockIdx.x * blockDim.x + threadIdx.x;
    int total = n * (DD / 4);
    if (i >= total) return;
    int j4 = i & 31;
    float4 su = ((const float4*)g_sum)[j4];
    float4 sq = ((const float4*)g_sumsq)[j4];
    float4 mu, rs;
    mu.x = su.x * inv_n; mu.y = su.y * inv_n; mu.z = su.z * inv_n; mu.w = su.w * inv_n;
    rs.x = rsqrtf(sq.x * inv_n - mu.x * mu.x + EPS);
    rs.y = rsqrtf(sq.y * inv_n - mu.y * mu.y + EPS);
    rs.z = rsqrtf(sq.z * inv_n - mu.z * mu.z + EPS);
    rs.w = rsqrtf(sq.w * inv_n - mu.w * mu.w + EPS);
    float4 v  = ((float4*)out)[i];
    float4 hv = ((const float4*)h)[i];
    float4 ga = ((const float4*)gamma)[j4];
    float4 be = ((const float4*)beta)[j4];
    v.x = hv.x + (v.x - mu.x) * rs.x * ga.x + be.x;
    v.y = hv.y + (v.y - mu.y) * rs.y * ga.y + be.y;
    v.z = hv.z + (v.z - mu.z) * rs.z * ga.z + be.z;
    v.w = hv.w + (v.w - mu.w) * rs.w * ga.w + be.w;
    ((float4*)out)[i] = v;
}

// ---------------- launch ----------------
extern "C" void kernel_launch(void* const* d_in, const int* in_sizes, int n_in,
                              void* d_out, int out_size) {
    const float* h     = (const float*)d_in[0];
    const int*   src   = (const int*)d_in[1];
    const int*   dst   = (const int*)d_in[2];
    const float* Wself = (const float*)d_in[3];
    const float* Wneigh= (const float*)d_in[4];
    const float* bias  = (const float*)d_in[5];
    const float* gamma = (const float*)d_in[6];
    const float* beta  = (const float*)d_in[7];
    float* out = (float*)d_out;
    int n = in_sizes[0] / DD;
    int e = in_sizes[1];

    int nscan = (n + SCAN_B - 1) / SCAN_B;

    k_detect<<<1, 32>>>(src, dst, e);
    k_h2h<<<1024, 256>>>(h, n);
    k_hist<<<(e + 255) / 256, 256>>>(dst, e, n);
    k_scan1<<<nscan, SCAN_B>>>(n);
    k_scan2<<<1, MAXPARTS>>>(nscan);
    k_scan3<<<nscan, SCAN_B>>>(n);
    k_fill<<<(e + 255) / 256, 256>>>(src, dst, e, n);
    k_gather<<<(n * 32 + 255) / 256, 256>>>(n);

    int ntiles = (n + MT - 1) / MT;
    size_t smem = (size_t)(128 * WP16 + MT * AP16) * sizeof(unsigned);
    cudaFuncSetAttribute(k_gemm_tc, cudaFuncAttributeMaxDynamicSharedMemorySize, (int)smem);
    k_gemm_tc<<<NSM, 256, smem>>>(Wself, Wneigh, bias, out, n, ntiles);

    k_final<<<(n * (DD / 4) + 255) / 256, 256>>>(h, gamma, beta, out, n, 1.0f / (float)n);
}

// round 12
// speedup vs baseline: 2.6155x; 1.1203x over previous
#include <cuda_runtime.h>
#include <cuda_fp16.h>
#include <cstdint>

#define DD 128
#define NMAX 100000
#define EMAX 3200000
#define EPS 1e-5f
#define SCAN_B 1024
#define MAXPARTS 128
#define NSM 148
#define MT 64          // rows per GEMM tile
#define WP16 136       // Ws pitch in uints (half2): 8t+g bank pattern
#define AP16 132       // As pitch in uints (half2): 4g+t bank pattern

// ---------------- scratch (no cudaMalloc allowed) ----------------
__device__ __align__(16) __half g_h16[(size_t)NMAX * DD];
__device__ __align__(16) __half g_n16[(size_t)NMAX * DD];
__device__ int g_esrc[EMAX];
__device__ int g_rank[EMAX];
__device__ int g_cnt[NMAX];
__device__ int g_off[NMAX + 1];
__device__ int g_part[MAXPARTS];
__device__ float g_sum[DD];
__device__ float g_sumsq[DD];
__device__ int g_is64;

__device__ __forceinline__ int edge_idx(const int* __restrict__ p, int i) {
    return g_is64 ? p[2 * i] : p[i];
}

__device__ __forceinline__ void mma_f16(float* c, const unsigned* a, unsigned b0, unsigned b1) {
    asm volatile("mma.sync.aligned.m16n8k16.row.col.f32.f16.f16.f32 "
                 "{%0,%1,%2,%3}, {%4,%5,%6,%7}, {%8,%9}, {%0,%1,%2,%3};"
                 : "+f"(c[0]), "+f"(c[1]), "+f"(c[2]), "+f"(c[3])
                 : "r"(a[0]), "r"(a[1]), "r"(a[2]), "r"(a[3]), "r"(b0), "r"(b1));
}

// ---------------- dtype probe + zero counters (must precede hist) ----------------
__global__ void k_detect(const int* __restrict__ s, const int* __restrict__ d, int e, int n) {
    int tid = blockIdx.x * blockDim.x + threadIdx.x;
    int nt = gridDim.x * blockDim.x;
    if (tid == 0) {
        int m = e < 64 ? e : 64;
        int odd = 0;
        for (int i = 0; i < m; i++) odd |= s[2 * i + 1] | d[2 * i + 1];
        g_is64 = (odd == 0) ? 1 : 0;
    }
    for (int i = tid; i < n; i += nt) g_cnt[i] = 0;
    if (tid < DD) { g_sum[tid] = 0.f; g_sumsq[tid] = 0.f; }
}

// ---------------- h -> fp16 mirror (side branch) ----------------
__global__ void k_h2h(const float* __restrict__ h, int n) {
    int tid = blockIdx.x * blockDim.x + threadIdx.x;
    int nt = gridDim.x * blockDim.x;
    int total = n * (DD / 4);
    for (int i = tid; i < total; i += nt) {
        float4 v = ((const float4*)h)[i];
        __half2 a = __floats2half2_rn(v.x, v.y);
        __half2 b = __floats2half2_rn(v.z, v.w);
        uint2 u;
        u.x = *(unsigned*)&a;
        u.y = *(unsigned*)&b;
        ((uint2*)g_h16)[i] = u;
    }
}

// ---------------- degree histogram + per-edge rank ----------------
__global__ void k_hist(const int* __restrict__ dst, int e, int n) {
    int i = blockIdx.x * blockDim.x + threadIdx.x;
    if (i >= e) return;
    int d = edge_idx(dst, i);
    int r = 0;
    if ((unsigned)d < (unsigned)n) r = atomicAdd(&g_cnt[d], 1);
    g_rank[i] = r;
}

// ---------------- decoupled scan ----------------
__global__ void __launch_bounds__(SCAN_B) k_scan1(int n) {
    __shared__ int sdata[SCAN_B];
    int tid = threadIdx.x;
    int i = blockIdx.x * SCAN_B + tid;
    int v = (i < n) ? g_cnt[i] : 0;
    sdata[tid] = v;
    __syncthreads();
    #pragma unroll
    for (int off = 1; off < SCAN_B; off <<= 1) {
        int t = (tid >= off) ? sdata[tid - off] : 0;
        __syncthreads();
        sdata[tid] += t;
        __syncthreads();
    }
    if (i < n) g_off[i + 1] = sdata[tid];
    if (tid == SCAN_B - 1) g_part[blockIdx.x] = sdata[tid];
}

__global__ void __launch_bounds__(MAXPARTS) k_scan2(int nblocks) {
    __shared__ int sdata[MAXPARTS];
    int tid = threadIdx.x;
    int v = (tid < nblocks) ? g_part[tid] : 0;
    sdata[tid] = v;
    __syncthreads();
    #pragma unroll
    for (int off = 1; off < MAXPARTS; off <<= 1) {
        int t = (tid >= off) ? sdata[tid - off] : 0;
        __syncthreads();
        sdata[tid] += t;
        __syncthreads();
    }
    if (tid < nblocks) g_part[tid] = sdata[tid] - v;
}

__global__ void __launch_bounds__(SCAN_B) k_scan3(int n) {
    int i = blockIdx.x * SCAN_B + threadIdx.x;
    if (i >= n) return;
    int carry = g_part[blockIdx.x];
    g_off[i + 1] += carry;
    if (i == 0) g_off[0] = 0;
}

// ---------------- bucket fill (atomic-free via rank) ----------------
__global__ void k_fill(const int* __restrict__ src,
                       const int* __restrict__ dst, int e, int n) {
    int i = blockIdx.x * blockDim.x + threadIdx.x;
    if (i >= e) return;
    int d = edge_idx(dst, i);
    int s = edge_idx(src, i);
    if ((unsigned)d >= (unsigned)n || (unsigned)s >= (unsigned)n) return;
    int pos = g_off[d] + g_rank[i];
    if ((unsigned)pos < (unsigned)EMAX) g_esrc[pos] = s;
}

// ---------------- warp-per-node gather (fp16 rows) -> fp16 neigh ----------------
__global__ void k_gather(int n) {
    int gw = (blockIdx.x * blockDim.x + threadIdx.x) >> 5;
    int lane = threadIdx.x & 31;
    if (gw >= n) return;
    int o0 = g_off[gw], o1 = g_off[gw + 1];
    int lane16 = lane & 15, half = lane >> 4;
    const uint4* h4 = (const uint4*)g_h16;   // 16B = 8 halves; 16 uint4 per row
    float acc[8];
    #pragma unroll
    for (int j = 0; j < 8; j++) acc[j] = 0.f;

    for (int jb = o0; jb < o1; jb += 32) {
        int myv = (jb + lane < o1) ? g_esrc[jb + lane] : 0;
        int cnt = min(32, o1 - jb);
        int k = 0;
        #pragma unroll 8
        for (; k + 2 <= cnt; k += 2) {
            int s = __shfl_sync(0xffffffffu, myv, k + half);
            uint4 raw = h4[s * 16 + lane16];
            const __half2* hp = (const __half2*)&raw;
            #pragma unroll
            for (int q = 0; q < 4; q++) {
                float2 f = __half22float2(hp[q]);
                acc[2 * q]     += f.x;
                acc[2 * q + 1] += f.y;
            }
        }
        if (k < cnt) {
            int s = __shfl_sync(0xffffffffu, myv, k);
            if (half == 0) {
                uint4 raw = h4[s * 16 + lane16];
                const __half2* hp = (const __half2*)&raw;
                #pragma unroll
                for (int q = 0; q < 4; q++) {
                    float2 f = __half22float2(hp[q]);
                    acc[2 * q]     += f.x;
                    acc[2 * q + 1] += f.y;
                }
            }
        }
    }

    #pragma unroll
    for (int j = 0; j < 8; j++)
        acc[j] += __shfl_xor_sync(0xffffffffu, acc[j], 16);

    if (half == 0) {
        float inv = 1.0f / fmaxf((float)(o1 - o0), 1.0f);
        uint4 o;
        __half2 p0 = __floats2half2_rn(acc[0] * inv, acc[1] * inv);
        __half2 p1 = __floats2half2_rn(acc[2] * inv, acc[3] * inv);
        __half2 p2 = __floats2half2_rn(acc[4] * inv, acc[5] * inv);
        __half2 p3 = __floats2half2_rn(acc[6] * inv, acc[7] * inv);
        o.x = *(unsigned*)&p0; o.y = *(unsigned*)&p1;
        o.z = *(unsigned*)&p2; o.w = *(unsigned*)&p3;
        ((uint4*)g_n16)[gw * 16 + lane16] = o;
    }
}

// ---------------- fp16 tensor-core dual-GEMM + bias + relu + BN sums ----------------
__global__ void __launch_bounds__(256) k_gemm_tc(
    const float* __restrict__ Wself, const float* __restrict__ Wneigh,
    const float* __restrict__ bias, float* __restrict__ out, int n, int ntiles)
{
    extern __shared__ unsigned smu[];
    unsigned* Wsu = smu;                 // 128 * WP16 uints (half2)
    unsigned* Asu = smu + 128 * WP16;    // MT * AP16 uints (half2)
    int tid = threadIdx.x;
    int wid = tid >> 5, lane = tid & 31;
    int g = lane >> 2, t = lane & 3;
    int wm = wid & 1, wn = wid >> 1;
    int colb = wn * 32;

    // stage W once: Ws16u[k2*WP16 + col] = half2(W[2k2][col], W[2k2+1][col])
    for (int i = tid; i < 128 * DD; i += 256) {
        int k2 = i >> 7, col = i & 127;
        int k = 2 * k2;
        const float* w0 = (k < DD) ? (Wself + k * DD) : (Wneigh + (k - DD) * DD);
        const float* w1 = w0 + DD;
        __half2 p = __floats2half2_rn(w0[col], w1[col]);
        Wsu[k2 * WP16 + col] = *(unsigned*)&p;
    }

    float bs[4][2];
    #pragma unroll
    for (int j = 0; j < 4; j++) {
        bs[j][0] = bias[colb + j * 8 + 2 * t];
        bs[j][1] = bias[colb + j * 8 + 2 * t + 1];
    }
    float csum[4][2] = {{0.f,0.f},{0.f,0.f},{0.f,0.f},{0.f,0.f}};
    float csq [4][2] = {{0.f,0.f},{0.f,0.f},{0.f,0.f},{0.f,0.f}};

    const uint4* h4 = (const uint4*)g_h16;
    const uint4* n4 = (const uint4*)g_n16;

    for (int tile = blockIdx.x; tile < ntiles; tile += gridDim.x) {
        int m0 = tile * MT;
        __syncthreads();
        #pragma unroll
        for (int it = 0; it < 8; it++) {
            int q = tid + it * 256;          // MT*32 = 2048 uint4
            int row = q >> 5, c4 = q & 31;
            int rg = m0 + row;
            uint4 v = make_uint4(0u, 0u, 0u, 0u);
            if (rg < n)
                v = (c4 < 16) ? h4[rg * 16 + c4] : n4[rg * 16 + (c4 - 16)];
            *(uint4*)&Asu[row * AP16 + c4 * 4] = v;
        }
        __syncthreads();

        float acc[2][4][4];
        #pragma unroll
        for (int i = 0; i < 2; i++)
            #pragma unroll
            for (int j = 0; j < 4; j++)
                #pragma unroll
                for (int q = 0; q < 4; q++) acc[i][j][q] = 0.f;

        #pragma unroll 4
        for (int kc = 0; kc < 16; kc++) {
            int k2b = kc * 8;
            unsigned a[2][4];
            #pragma unroll
            for (int i = 0; i < 2; i++) {
                int rb = (wm * 32 + i * 16 + g) * AP16 + k2b + t;
                a[i][0] = Asu[rb];
                a[i][1] = Asu[rb + 8 * AP16];
                a[i][2] = Asu[rb + 4];
                a[i][3] = Asu[rb + 8 * AP16 + 4];
            }
            #pragma unroll
            for (int j = 0; j < 4; j++) {
                int col = colb + j * 8 + g;
                unsigned b0 = Wsu[(k2b + t) * WP16 + col];
                unsigned b1 = Wsu[(k2b + 4 + t) * WP16 + col];
                mma_f16(acc[0][j], a[0], b0, b1);
                mma_f16(acc[1][j], a[1], b0, b1);
            }
        }

        #pragma unroll
        for (int i = 0; i < 2; i++) {
            int row0 = m0 + wm * 32 + i * 16 + g;
            #pragma unroll
            for (int j = 0; j < 4; j++) {
                int col = colb + j * 8 + 2 * t;
                float c0 = fmaxf(acc[i][j][0] + bs[j][0], 0.f);
                float c1 = fmaxf(acc[i][j][1] + bs[j][1], 0.f);
                float c2 = fmaxf(acc[i][j][2] + bs[j][0], 0.f);
                float c3 = fmaxf(acc[i][j][3] + bs[j][1], 0.f);
                if (row0 < n) {
                    *(float2*)&out[(size_t)row0 * DD + col] = make_float2(c0, c1);
                    csum[j][0] += c0; csq[j][0] += c0 * c0;
                    csum[j][1] += c1; csq[j][1] += c1 * c1;
                }
                if (row0 + 8 < n) {
                    *(float2*)&out[(size_t)(row0 + 8) * DD + col] = make_float2(c2, c3);
                    csum[j][0] += c2; csq[j][0] += c2 * c2;
                    csum[j][1] += c3; csq[j][1] += c3 * c3;
                }
            }
        }
    }

    #pragma unroll
    for (int j = 0; j < 4; j++)
        #pragma unroll
        for (int p = 0; p < 2; p++) {
            float s = csum[j][p], q = csq[j][p];
            #pragma unroll
            for (int off = 16; off >= 4; off >>= 1) {
                s += __shfl_down_sync(0xffffffffu, s, off);
                q += __shfl_down_sync(0xffffffffu, q, off);
            }
            if (g == 0) {
                int col = colb + j * 8 + 2 * t + p;
                atomicAdd(&g_sum[col], s);
                atomicAdd(&g_sumsq[col], q);
            }
        }
}

// ---------------- normalize + residual (stats computed inline) ----------------
__global__ void k_final(const float* __restrict__ h, const float* __restrict__ gamma,
                        const float* __restrict__ beta, float* __restrict__ out,
                        int n, float inv_n) {
    int i = blockIdx.x * blockDim.x + threadIdx.x;
    int total = n * (DD / 4);
    if (i >= total) return;
    int j4 = i & 31;
    float4 su = ((const float4*)g_sum)[j4];
    float4 sq = ((const float4*)g_sumsq)[j4];
    float4 mu, rs;
    mu.x = su.x * inv_n; mu.y = su.y * inv_n; mu.z = su.z * inv_n; mu.w = su.w * inv_n;
    rs.x = rsqrtf(sq.x * inv_n - mu.x * mu.x + EPS);
    rs.y = rsqrtf(sq.y * inv_n - mu.y * mu.y + EPS);
    rs.z = rsqrtf(sq.z * inv_n - mu.z * mu.z + EPS);
    rs.w = rsqrtf(sq.w * inv_n - mu.w * mu.w + EPS);
    float4 v  = ((float4*)out)[i];
    float4 hv = ((const float4*)h)[i];
    float4 ga = ((const float4*)gamma)[j4];
    float4 be = ((const float4*)beta)[j4];
    v.x = hv.x + (v.x - mu.x) * rs.x * ga.x + be.x;
    v.y = hv.y + (v.y - mu.y) * rs.y * ga.y + be.y;
    v.z = hv.z + (v.z - mu.z) * rs.z * ga.z + be.z;
    v.w = hv.w + (v.w - mu.w) * rs.w * ga.w + be.w;
    ((float4*)out)[i] = v;
}

// ---------------- launch ----------------
extern "C" void kernel_launch(void* const* d_in, const int* in_sizes, int n_in,
                              void* d_out, int out_size) {
    const float* h     = (const float*)d_in[0];
    const int*   src   = (const int*)d_in[1];
    const int*   dst   = (const int*)d_in[2];
    const float* Wself = (const float*)d_in[3];
    const float* Wneigh= (const float*)d_in[4];
    const float* bias  = (const float*)d_in[5];
    const float* gamma = (const float*)d_in[6];
    const float* beta  = (const float*)d_in[7];
    float* out = (float*)d_out;
    int n = in_sizes[0] / DD;
    int e = in_sizes[1];

    // one-time side stream + events (created on first, non-captured call)
    static cudaStream_t s2 = nullptr;
    static cudaEvent_t evFork = nullptr, evJoin = nullptr;
    if (s2 == nullptr) {
        cudaStreamCreateWithFlags(&s2, cudaStreamNonBlocking);
        cudaEventCreateWithFlags(&evFork, cudaEventDisableTiming);
        cudaEventCreateWithFlags(&evJoin, cudaEventDisableTiming);
    }

    int nscan = (n + SCAN_B - 1) / SCAN_B;

    k_detect<<<512, 256>>>(src, dst, e, n);

    // fork: h2h runs parallel with the CSR-build chain
    cudaEventRecord(evFork, 0);
    cudaStreamWaitEvent(s2, evFork, 0);
    k_h2h<<<1024, 256, 0, s2>>>(h, n);
    cudaEventRecord(evJoin, s2);

    k_hist<<<(e + 255) / 256, 256>>>(dst, e, n);
    k_scan1<<<nscan, SCAN_B>>>(n);
    k_scan2<<<1, MAXPARTS>>>(nscan);
    k_scan3<<<nscan, SCAN_B>>>(n);
    k_fill<<<(e + 255) / 256, 256>>>(src, dst, e, n);

    // join: gather needs both h16 and the CSR
    cudaStreamWaitEvent(0, evJoin, 0);
    k_gather<<<(n * 32 + 255) / 256, 256>>>(n);

    int ntiles = (n + MT - 1) / MT;
    size_t smem = (size_t)(128 * WP16 + MT * AP16) * sizeof(unsigned);
    cudaFuncSetAttribute(k_gemm_tc, cudaFuncAttributeMaxDynamicSharedMemorySize, (int)smem);
    k_gemm_tc<<<2 * NSM, 256, smem>>>(Wself, Wneigh, bias, out, n, ntiles);

    k_final<<<(n * (DD / 4) + 255) / 256, 256>>>(h, gamma, beta, out, n, 1.0f / (float)n);
}